// round 9
// baseline (speedup 1.0000x reference)
#include <cuda_runtime.h>
#include <cuda_bf16.h>
#include <cstdint>

#define N_USER 100000
#define N_GAME 50000
#define DDIM   256
#define EMAX   200000
#define UBLK   ((N_USER + 127) / 128)   // 782
#define GBLK   ((N_GAME + 127) / 128)   // 391

// ---------------- scratch (device globals) ----------------
__device__ int   g_rp_u[N_USER + 1];
__device__ int   g_rp_g[N_GAME + 1];
__device__ int   g_cur_u[N_USER];
__device__ int   g_cur_g[N_GAME];
__device__ int   g_srcs_u[EMAX];
__device__ int   g_srcs_g[EMAX];
__device__ int   g_part_u[128];
__device__ int   g_part_g[128];
__device__ float g_tmpA[DDIM * DDIM];   // Wm_played @ Wout_game
__device__ float g_tmpB[DDIM * DDIM];   // Wm_rev @ Wout_user
__device__ __nv_bfloat16 g_Wub[DDIM * DDIM];  // bf16(0.125 * Wv_game @ tmpB)
__device__ __nv_bfloat16 g_Wgb[DDIM * DDIM];  // bf16(0.125 * Wv_user @ tmpA)
__device__ float g_eu[DDIM];
__device__ float g_eg[DDIM];

// ---------------- kernel 0: 64x64-tile weight GEMM pair + edge histogram ----
__global__ void k0_gemm_hist(const float* __restrict__ A0, const float* __restrict__ B0,
                             float* __restrict__ C0,
                             const float* __restrict__ A1, const float* __restrict__ B1,
                             float* __restrict__ C1,
                             const int* __restrict__ pd, const int* __restrict__ rd, int E,
                             int* __restrict__ rp_g, int* __restrict__ rp_u)
{
    if (blockIdx.z >= 2) {
        // histogram over 32 blocks
        int base = ((blockIdx.z - 2) * 16 + blockIdx.y * 4 + blockIdx.x) * 256 + threadIdx.x;
        for (int i = base; i < E; i += 32 * 256) {
            atomicAdd(&rp_g[pd[i] + 1], 1);
            atomicAdd(&rp_u[rd[i] + 1], 1);
        }
        return;
    }
    const float* A = blockIdx.z ? A1 : A0;
    const float* B = blockIdx.z ? B1 : B0;
    float*       C = blockIdx.z ? C1 : C0;
    __shared__ float As[16][64];
    __shared__ float Bs[16][64];
    const int tid = threadIdx.x;
    const int tx = tid & 15, ty = tid >> 4;
    const int row0 = blockIdx.y * 64, col0 = blockIdx.x * 64;
    const int arow = tid >> 2, ac4 = (tid & 3) * 4;
    const int brow = tid >> 4, bc4 = (tid & 15) * 4;
    float acc[4][4];
#pragma unroll
    for (int i = 0; i < 4; i++)
#pragma unroll
        for (int j = 0; j < 4; j++) acc[i][j] = 0.f;

    for (int kk = 0; kk < 256; kk += 16) {
        float4 av = *(const float4*)(A + (size_t)(row0 + arow) * 256 + kk + ac4);
        As[ac4 + 0][arow] = av.x;
        As[ac4 + 1][arow] = av.y;
        As[ac4 + 2][arow] = av.z;
        As[ac4 + 3][arow] = av.w;
        float4 bv = *(const float4*)(B + (size_t)(kk + brow) * 256 + col0 + bc4);
        *(float4*)&Bs[brow][bc4] = bv;
        __syncthreads();
#pragma unroll
        for (int k = 0; k < 16; k++) {
            float4 a = *(const float4*)&As[k][ty * 4];
            float4 b = *(const float4*)&Bs[k][tx * 4];
            float ar[4] = {a.x, a.y, a.z, a.w};
            float br[4] = {b.x, b.y, b.z, b.w};
#pragma unroll
            for (int i = 0; i < 4; i++)
#pragma unroll
                for (int j = 0; j < 4; j++) acc[i][j] += ar[i] * br[j];
        }
        __syncthreads();
    }
#pragma unroll
    for (int i = 0; i < 4; i++) {
        float4 o = make_float4(acc[i][0], acc[i][1], acc[i][2], acc[i][3]);
        *(float4*)(C + (size_t)(row0 + ty * 4 + i) * 256 + col0 + tx * 4) = o;
    }
}

// ---------------- kernel 1: bf16 weight GEMM pair + fused bias combo ----------
__global__ void k1_gemmbf_combo(const float* __restrict__ A0, const float* __restrict__ B0,
                                __nv_bfloat16* __restrict__ C0,
                                const float* __restrict__ A1, const float* __restrict__ B1,
                                __nv_bfloat16* __restrict__ C1, float scale,
                                const float* __restrict__ bv0, const float* __restrict__ T0,
                                const float* __restrict__ bm0, const float* __restrict__ W0,
                                float* __restrict__ e0,
                                const float* __restrict__ bv1, const float* __restrict__ T1,
                                const float* __restrict__ bm1, const float* __restrict__ W1,
                                float* __restrict__ e1)
{
    if (blockIdx.z == 2) {
        if (blockIdx.y != 0 || blockIdx.x >= 2) return;
        const float* bv = blockIdx.x ? bv1 : bv0;
        const float* T  = blockIdx.x ? T1  : T0;
        const float* bm = blockIdx.x ? bm1 : bm0;
        const float* W  = blockIdx.x ? W1  : W0;
        float*       e  = blockIdx.x ? e1  : e0;
        int n = threadIdx.x;
        float acc = 0.f;
#pragma unroll 8
        for (int j = 0; j < 256; j++)
            acc += bv[j] * T[j * 256 + n] + bm[j] * W[j * 256 + n];
        e[n] = 0.125f * acc;
        return;
    }
    const float* A = blockIdx.z ? A1 : A0;
    const float* B = blockIdx.z ? B1 : B0;
    __nv_bfloat16* C = blockIdx.z ? C1 : C0;
    __shared__ float As[16][64];
    __shared__ float Bs[16][64];
    const int tid = threadIdx.x;
    const int tx = tid & 15, ty = tid >> 4;
    const int row0 = blockIdx.y * 64, col0 = blockIdx.x * 64;
    const int arow = tid >> 2, ac4 = (tid & 3) * 4;
    const int brow = tid >> 4, bc4 = (tid & 15) * 4;
    float acc[4][4];
#pragma unroll
    for (int i = 0; i < 4; i++)
#pragma unroll
        for (int j = 0; j < 4; j++) acc[i][j] = 0.f;

    for (int kk = 0; kk < 256; kk += 16) {
        float4 av = *(const float4*)(A + (size_t)(row0 + arow) * 256 + kk + ac4);
        As[ac4 + 0][arow] = av.x;
        As[ac4 + 1][arow] = av.y;
        As[ac4 + 2][arow] = av.z;
        As[ac4 + 3][arow] = av.w;
        float4 bv = *(const float4*)(B + (size_t)(kk + brow) * 256 + col0 + bc4);
        *(float4*)&Bs[brow][bc4] = bv;
        __syncthreads();
#pragma unroll
        for (int k = 0; k < 16; k++) {
            float4 a = *(const float4*)&As[k][ty * 4];
            float4 b = *(const float4*)&Bs[k][tx * 4];
            float ar[4] = {a.x, a.y, a.z, a.w};
            float br[4] = {b.x, b.y, b.z, b.w};
#pragma unroll
            for (int i = 0; i < 4; i++)
#pragma unroll
                for (int j = 0; j < 4; j++) acc[i][j] += ar[i] * br[j];
        }
        __syncthreads();
    }
#pragma unroll
    for (int i = 0; i < 4; i++) {
#pragma unroll
        for (int j = 0; j < 4; j++)
            C[(size_t)(row0 + ty * 4 + i) * 256 + col0 + tx * 4 + j] =
                __float2bfloat16(acc[i][j] * scale);
    }
}

// ---------------- scan kernels (unchanged) ----------------
__global__ void scanA(const int* __restrict__ in_u, int len_u, int* __restrict__ part_u,
                      const int* __restrict__ in_g, int len_g, int* __restrict__ part_g)
{
    const int* in  = blockIdx.y ? in_g  : in_u;
    const int len  = blockIdx.y ? len_g : len_u;
    int* part      = blockIdx.y ? part_g : part_u;
    int t = threadIdx.x;
    int idx = blockIdx.x * 1024 + t;
    int v = (idx < len) ? in[idx] : 0;
    int lane = t & 31, wid = t >> 5;
#pragma unroll
    for (int o = 16; o; o >>= 1) v += __shfl_down_sync(0xFFFFFFFFu, v, o);
    __shared__ int ws[32];
    if (lane == 0) ws[wid] = v;
    __syncthreads();
    if (wid == 0) {
        int s = ws[lane];
#pragma unroll
        for (int o = 16; o; o >>= 1) s += __shfl_down_sync(0xFFFFFFFFu, s, o);
        if (lane == 0) part[blockIdx.x] = s;
    }
}

__global__ void scanC(int* __restrict__ rp_u, int len_u, const int* __restrict__ part_u,
                      int* __restrict__ cur_u,
                      int* __restrict__ rp_g, int len_g, const int* __restrict__ part_g,
                      int* __restrict__ cur_g)
{
    int* rp         = blockIdx.y ? rp_g  : rp_u;
    const int len   = blockIdx.y ? len_g : len_u;
    const int* part = blockIdx.y ? part_g : part_u;
    int* cur        = blockIdx.y ? cur_g : cur_u;

    __shared__ int sp[128];
    int t = threadIdx.x;
    if (t < 128) sp[t] = (t < (int)gridDim.x) ? part[t] : 0;
    __syncthreads();
    int offset = 0;
    for (int j = 0; j < (int)blockIdx.x; j++) offset += sp[j];

    int idx = blockIdx.x * 1024 + t;
    int x = (idx < len) ? rp[idx] : 0;
    int lane = t & 31, wid = t >> 5;
#pragma unroll
    for (int o = 1; o < 32; o <<= 1) {
        int n = __shfl_up_sync(0xFFFFFFFFu, x, o);
        if (lane >= o) x += n;
    }
    __shared__ int wsum[32];
    if (lane == 31) wsum[wid] = x;
    __syncthreads();
    if (wid == 0) {
        int y = wsum[lane];
#pragma unroll
        for (int o = 1; o < 32; o <<= 1) {
            int n = __shfl_up_sync(0xFFFFFFFFu, y, o);
            if (lane >= o) y += n;
        }
        wsum[lane] = y;
    }
    __syncthreads();
    int incl = x + (wid > 0 ? wsum[wid - 1] : 0) + offset;
    if (idx < len) {
        rp[idx] = incl;
        if (idx < len - 1) cur[idx] = incl;
    }
}

__global__ void bin_kernel(const int* __restrict__ ps, const int* __restrict__ pd,
                           const int* __restrict__ rs, const int* __restrict__ rd, int E,
                           int* __restrict__ cur_g, int* __restrict__ srcs_g,
                           int* __restrict__ cur_u, int* __restrict__ srcs_u)
{
    int i = blockIdx.x * blockDim.x + threadIdx.x;
    if (i < E) {
        int dg = pd[i];
        int p = atomicAdd(&cur_g[dg], 1);
        srcs_g[p] = ps[i];
        int du = rd[i];
        int q = atomicAdd(&cur_u[du], 1);
        srcs_u[q] = rs[i];
    }
}

// ---------------- fused edge-parallel gather + MMA + epilogue (both passes) ----
__device__ __forceinline__ uint32_t smem_u32(const void* p)
{
    return (uint32_t)__cvta_generic_to_shared(p);
}

__device__ __forceinline__ void ldsm_x4(uint32_t* r, uint32_t addr)
{
    asm volatile("ldmatrix.sync.aligned.m8n8.x4.shared.b16 {%0,%1,%2,%3}, [%4];"
                 : "=r"(r[0]), "=r"(r[1]), "=r"(r[2]), "=r"(r[3]) : "r"(addr));
}

__device__ __forceinline__ void ldsm_x4_t(uint32_t* r, uint32_t addr)
{
    asm volatile("ldmatrix.sync.aligned.m8n8.x4.trans.shared.b16 {%0,%1,%2,%3}, [%4];"
                 : "=r"(r[0]), "=r"(r[1]), "=r"(r[2]), "=r"(r[3]) : "r"(addr));
}

__device__ __forceinline__ void mma_bf16(float* c, const uint32_t* a, const uint32_t* b)
{
    asm volatile("mma.sync.aligned.m16n8k16.row.col.f32.bf16.bf16.f32 "
                 "{%0,%1,%2,%3}, {%4,%5,%6,%7}, {%8,%9}, {%0,%1,%2,%3};"
                 : "+f"(c[0]), "+f"(c[1]), "+f"(c[2]), "+f"(c[3])
                 : "r"(a[0]), "r"(a[1]), "r"(a[2]), "r"(a[3]), "r"(b[0]), "r"(b[1]));
}

// smem layout (bytes):
//   Af32: 128 rows x 257 words fp32 (permuted columns)  = 131584
//   Abf : 128 rows x 264 bf16 (528B stride)              =  67584
//   B   : 2 x 16 x 264 bf16                              =  16896
//   srp : 129 ints (+pad)                                =    528
//   onS : 128 floats                                     =    512
#define AF32_STRIDE  257
#define SM_ABF_OFF   131584
#define SM_B_OFF     (SM_ABF_OFF + 128 * 264 * 2)   // 199168
#define SM_SRP_OFF   (SM_B_OFF + 2 * 16 * 264 * 2)  // 216064
#define SM_ON_OFF    (SM_SRP_OFF + 132 * 4)         // 216592
#define SM_TOTAL     (SM_ON_OFF + 128 * 4)          // 217104

__global__ __launch_bounds__(512, 1)
void fused_all(const int* __restrict__ rp_u, const int* __restrict__ srcs_u,
               const int* __restrict__ rp_g, const int* __restrict__ srcs_g,
               const float* __restrict__ x_user, const float* __restrict__ x_game,
               const __nv_bfloat16* __restrict__ Wub, const __nv_bfloat16* __restrict__ Wgb,
               const float* __restrict__ eu, const float* __restrict__ eg,
               const float* __restrict__ bout_u, const float* __restrict__ bout_g,
               float* __restrict__ out)
{
    extern __shared__ char smem[];
    float* Af32 = (float*)smem;
    __nv_bfloat16* Abf = (__nv_bfloat16*)(smem + SM_ABF_OFF);
    __nv_bfloat16* Bsm = (__nv_bfloat16*)(smem + SM_B_OFF);
    int* srp  = (int*)(smem + SM_SRP_OFF);
    float* onS = (float*)(smem + SM_ON_OFF);

    const int tid = threadIdx.x;
    const int lane = tid & 31;
    const int warp = tid >> 5;

    // ---- pass selection ----
    const bool isU = (blockIdx.x < UBLK);
    const int bm0 = (isU ? blockIdx.x : blockIdx.x - UBLK) * 128;
    const int M = isU ? N_USER : N_GAME;
    const int* rowptr = isU ? rp_u : rp_g;
    const int* srcs   = isU ? srcs_u : srcs_g;
    const float* Xsrc = isU ? x_game : x_user;
    const float* Xres = isU ? x_user : x_game;
    const __nv_bfloat16* Wb = isU ? Wub : Wgb;
    const float* extra = isU ? eu : eg;
    const float* bout  = isU ? bout_u : bout_g;
    float* Outb = isU ? out : out + (size_t)N_USER * DDIM;

    // ---- stage: srp, zero Af32, B tile 0 ----
    for (int i = tid; i < 129; i += 512) {
        int rr = bm0 + i;
        if (rr > M) rr = M;
        srp[i] = rowptr[rr];
    }
    for (int i = tid; i < 128 * AF32_STRIDE; i += 512) Af32[i] = 0.f;

    const int brow = tid >> 5, bq = tid & 31;
    const __nv_bfloat16* bptr = Wb + (size_t)brow * 256 + bq * 8;
    {
        uint4 b0 = *(const uint4*)bptr;
        *(uint4*)(Bsm + brow * 264 + bq * 8) = b0;
    }
    __syncthreads();

    // ---- phase 1: edge-parallel gather with smem f32 atomics ----
    {
        const int eb = srp[0], ee = srp[128];
        const int Et = ee - eb;
        const int chunk = (Et + 15) >> 4;
        const int we0 = eb + warp * chunk;
        const int we1 = min(we0 + chunk, ee);
        if (we0 < we1) {
            int lo = 0, hi = 127;
            while (lo < hi) {
                int mid = (lo + hi + 1) >> 1;
                if (srp[mid] <= we0) lo = mid; else hi = mid - 1;
            }
            int row = lo;
            int nxt = srp[row + 1];
            float4 accA = make_float4(0.f, 0.f, 0.f, 0.f);
            float4 accB = make_float4(0.f, 0.f, 0.f, 0.f);
            bool dirty = false;
            const float4* X4 = (const float4*)Xsrc;

            for (int b0i = we0; b0i < we1; b0i += 32) {
                int nb = min(32, we1 - b0i);
                int sv = (lane < nb) ? srcs[b0i + lane] : 0;
                int s0 = __shfl_sync(0xFFFFFFFFu, sv, 0);
                float4 u0 = X4[(size_t)s0 * 64 + lane];
                float4 v0 = X4[(size_t)s0 * 64 + 32 + lane];
                for (int t = 0; t < nb; t++) {
                    float4 u1, v1;
                    if (t + 1 < nb) {
                        int sn = __shfl_sync(0xFFFFFFFFu, sv, t + 1);
                        u1 = X4[(size_t)sn * 64 + lane];
                        v1 = X4[(size_t)sn * 64 + 32 + lane];
                    }
                    int e = b0i + t;
                    while (e >= nxt) {
                        if (dirty) {
                            float* bp = Af32 + row * AF32_STRIDE + lane;
                            atomicAdd(bp + 0,   accA.x); atomicAdd(bp + 32,  accA.y);
                            atomicAdd(bp + 64,  accA.z); atomicAdd(bp + 96,  accA.w);
                            atomicAdd(bp + 128, accB.x); atomicAdd(bp + 160, accB.y);
                            atomicAdd(bp + 192, accB.z); atomicAdd(bp + 224, accB.w);
                            accA = make_float4(0.f, 0.f, 0.f, 0.f);
                            accB = make_float4(0.f, 0.f, 0.f, 0.f);
                            dirty = false;
                        }
                        row++;
                        nxt = srp[row + 1];
                    }
                    accA.x += u0.x; accA.y += u0.y; accA.z += u0.z; accA.w += u0.w;
                    accB.x += v0.x; accB.y += v0.y; accB.z += v0.z; accB.w += v0.w;
                    dirty = true;
                    u0 = u1; v0 = v1;
                }
            }
            if (dirty) {
                float* bp = Af32 + row * AF32_STRIDE + lane;
                atomicAdd(bp + 0,   accA.x); atomicAdd(bp + 32,  accA.y);
                atomicAdd(bp + 64,  accA.z); atomicAdd(bp + 96,  accA.w);
                atomicAdd(bp + 128, accB.x); atomicAdd(bp + 160, accB.y);
                atomicAdd(bp + 192, accB.z); atomicAdd(bp + 224, accB.w);
            }
        }
    }
    __syncthreads();

    // ---- phase 1b: normalize + fp32 -> bf16 A tile (warp-per-row, un-permute) ----
#pragma unroll 1
    for (int i = 0; i < 8; i++) {
        int r = warp * 8 + i;
        int deg = srp[r + 1] - srp[r];
        float inv = 1.0f / (float)(deg > 1 ? deg : 1);
        const float* src = Af32 + r * AF32_STRIDE + lane;
        float f0 = src[0]   * inv, f1 = src[32]  * inv, f2 = src[64]  * inv, f3 = src[96]  * inv;
        float g0 = src[128] * inv, g1 = src[160] * inv, g2 = src[192] * inv, g3 = src[224] * inv;
        __nv_bfloat162 h0 = __floats2bfloat162_rn(f0, f1);
        __nv_bfloat162 h1 = __floats2bfloat162_rn(f2, f3);
        __nv_bfloat162 h2 = __floats2bfloat162_rn(g0, g1);
        __nv_bfloat162 h3 = __floats2bfloat162_rn(g2, g3);
        uint2 w0; w0.x = *(uint32_t*)&h0; w0.y = *(uint32_t*)&h1;
        uint2 w1; w1.x = *(uint32_t*)&h2; w1.y = *(uint32_t*)&h3;
        *(uint2*)(Abf + r * 264 + lane * 4) = w0;
        *(uint2*)(Abf + r * 264 + 128 + lane * 4) = w1;
        if (lane == 0) onS[r] = (deg > 0) ? 1.0f : 0.0f;
    }
    __syncthreads();

    // ---- phase 2: MMA ----
    const int wm0 = (warp >> 2) * 32;
    const int wn0 = (warp & 3) * 64;

    float acc[2][8][4];
#pragma unroll
    for (int mt = 0; mt < 2; mt++)
#pragma unroll
        for (int nt = 0; nt < 8; nt++)
#pragma unroll
            for (int j = 0; j < 4; j++) acc[mt][nt][j] = 0.f;

    const uint32_t aBase = smem_u32(Abf);
    const uint32_t bBase0 = smem_u32(Bsm);
    const uint32_t bBase1 = bBase0 + 16 * 528u;

    uint4 bReg;
    for (int it = 0; it < 16; it++) {
        if (it < 15)
            bReg = *(const uint4*)(bptr + (size_t)(it + 1) * 16 * 256);

        {
            const uint32_t bB = (it & 1) ? bBase1 : bBase0;
            uint32_t ra[2][4];
#pragma unroll
            for (int mt = 0; mt < 2; mt++) {
                uint32_t addr = aBase + (uint32_t)(wm0 + mt * 16 + (lane & 15)) * 528u
                              + (uint32_t)(lane >> 4) * 16u + (uint32_t)it * 32u;
                ldsm_x4(ra[mt], addr);
            }
#pragma unroll
            for (int p = 0; p < 4; p++) {
                uint32_t rb[4];
                uint32_t addr = bB + (uint32_t)(lane & 15) * 528u
                              + (uint32_t)(wn0 + p * 16 + ((lane >> 4) * 8)) * 2u;
                ldsm_x4_t(rb, addr);
#pragma unroll
                for (int mt = 0; mt < 2; mt++) {
                    mma_bf16(acc[mt][2 * p + 0], ra[mt], rb + 0);
                    mma_bf16(acc[mt][2 * p + 1], ra[mt], rb + 2);
                }
            }
        }

        if (it < 15) {
            int nb = (it + 1) & 1;
            *(uint4*)(Bsm + nb * 16 * 264 + brow * 264 + bq * 8) = bReg;
            __syncthreads();
        }
    }

    // ---- epilogue ----
    const int groupID = lane >> 2;
    const int tig = lane & 3;
#pragma unroll
    for (int nt = 0; nt < 8; nt++) {
        const int col = wn0 + nt * 8 + tig * 2;
        const float2 bo = *(const float2*)(bout + col);
        const float2 ev = *(const float2*)(extra + col);
#pragma unroll
        for (int mt = 0; mt < 2; mt++) {
            const int lrow0 = wm0 + mt * 16 + groupID;
            const int row0 = bm0 + lrow0;
            if (row0 < M) {
                float on = onS[lrow0];
                float2 xv = *(const float2*)(Xres + (size_t)row0 * 256 + col);
                float2 o;
                o.x = fmaxf(acc[mt][nt][0] + bo.x + on * ev.x + xv.x, 0.f);
                o.y = fmaxf(acc[mt][nt][1] + bo.y + on * ev.y + xv.y, 0.f);
                *(float2*)(Outb + (size_t)row0 * 256 + col) = o;
            }
            const int lrow1 = lrow0 + 8;
            const int row1 = row0 + 8;
            if (row1 < M) {
                float on = onS[lrow1];
                float2 xv = *(const float2*)(Xres + (size_t)row1 * 256 + col);
                float2 o;
                o.x = fmaxf(acc[mt][nt][2] + bo.x + on * ev.x + xv.x, 0.f);
                o.y = fmaxf(acc[mt][nt][3] + bo.y + on * ev.y + xv.y, 0.f);
                *(float2*)(Outb + (size_t)row1 * 256 + col) = o;
            }
        }
    }
}

// ---------------- host launch ----------------
extern "C" void kernel_launch(void* const* d_in, const int* in_sizes, int n_in,
                              void* d_out, int out_size)
{
    const float* x_user    = (const float*)d_in[0];
    const float* x_game    = (const float*)d_in[1];
    const float* Wv_user   = (const float*)d_in[6];
    const float* bv_user   = (const float*)d_in[7];
    const float* Wout_user = (const float*)d_in[8];
    const float* bout_user = (const float*)d_in[9];
    const float* Wv_game   = (const float*)d_in[14];
    const float* bv_game   = (const float*)d_in[15];
    const float* Wout_game = (const float*)d_in[16];
    const float* bout_game = (const float*)d_in[17];
    const float* Wm_played = (const float*)d_in[20];
    const float* bm_played = (const float*)d_in[21];
    const float* Wm_rev    = (const float*)d_in[24];
    const float* bm_rev    = (const float*)d_in[25];
    const int* ps = (const int*)d_in[26];
    const int* pd = (const int*)d_in[27];
    const int* rs = (const int*)d_in[28];
    const int* rd = (const int*)d_in[29];
    const int E = in_sizes[26];

    float* out = (float*)d_out;

    float *tmpA, *tmpB, *eu, *eg;
    int *rp_u, *rp_g, *cur_u, *cur_g, *srcs_u, *srcs_g, *part_u, *part_g;
    __nv_bfloat16 *Wub, *Wgb;
    cudaGetSymbolAddress((void**)&rp_u,   g_rp_u);
    cudaGetSymbolAddress((void**)&rp_g,   g_rp_g);
    cudaGetSymbolAddress((void**)&cur_u,  g_cur_u);
    cudaGetSymbolAddress((void**)&cur_g,  g_cur_g);
    cudaGetSymbolAddress((void**)&srcs_u, g_srcs_u);
    cudaGetSymbolAddress((void**)&srcs_g, g_srcs_g);
    cudaGetSymbolAddress((void**)&part_u, g_part_u);
    cudaGetSymbolAddress((void**)&part_g, g_part_g);
    cudaGetSymbolAddress((void**)&tmpA,   g_tmpA);
    cudaGetSymbolAddress((void**)&tmpB,   g_tmpB);
    cudaGetSymbolAddress((void**)&Wub,    g_Wub);
    cudaGetSymbolAddress((void**)&Wgb,    g_Wgb);
    cudaGetSymbolAddress((void**)&eu,     g_eu);
    cudaGetSymbolAddress((void**)&eg,     g_eg);

    cudaFuncSetAttribute(fused_all,
                         cudaFuncAttributeMaxDynamicSharedMemorySize, SM_TOTAL);

    // memsets (count toward ncu skip but are not kernels)
    cudaMemsetAsync(rp_u, 0, (size_t)(N_USER + 1) * sizeof(int));
    cudaMemsetAsync(rp_g, 0, (size_t)(N_GAME + 1) * sizeof(int));

    const int len_u = N_USER + 1, len_g = N_GAME + 1;
    const int sgx = (len_u + 1023) / 1024;

    // kernel 0: weight-chain GEMM pair (64x64 tiles) + histogram
    k0_gemm_hist<<<dim3(4, 4, 4), 256>>>(Wm_played, Wout_game, tmpA,
                                         Wm_rev, Wout_user, tmpB,
                                         pd, rd, E, rp_g, rp_u);
    // kernel 1: bf16 weight GEMM pair + bias combo
    k1_gemmbf_combo<<<dim3(4, 4, 3), 256>>>(Wv_user, tmpA, Wgb,
                                            Wv_game, tmpB, Wub, 0.125f,
                                            bv_user, tmpA, bm_played, Wout_game, eg,
                                            bv_game, tmpB, bm_rev, Wout_user, eu);
    // kernel 2,3: scan
    scanA<<<dim3(sgx, 2), 1024>>>(rp_u, len_u, part_u, rp_g, len_g, part_g);
    scanC<<<dim3(sgx, 2), 1024>>>(rp_u, len_u, part_u, cur_u, rp_g, len_g, part_g, cur_g);
    // kernel 4: bin edges into CSR
    bin_kernel<<<(E + 255) / 256, 256>>>(ps, pd, rs, rd, E, cur_g, srcs_g, cur_u, srcs_u);
    // kernel 5 (profiled): fused gather + MMA + epilogue, both passes
    fused_all<<<UBLK + GBLK, 512, SM_TOTAL>>>(rp_u, srcs_u, rp_g, srcs_g,
                                              x_user, x_game, Wub, Wgb,
                                              eu, eg, bout_user, bout_game, out);
}

// round 11
// speedup vs baseline: 1.2905x; 1.2905x over previous
#include <cuda_runtime.h>
#include <cuda_bf16.h>
#include <cstdint>

#define N_USER 100000
#define N_GAME 50000
#define DDIM   256
#define EMAX   200000
#define UBLK   ((N_USER + 127) / 128)   // 782
#define GBLK   ((N_GAME + 127) / 128)   // 391

// ---------------- scratch (device globals) ----------------
__device__ int   g_rp_u[N_USER + 1];
__device__ int   g_rp_g[N_GAME + 1];
__device__ int   g_cur_u[N_USER];
__device__ int   g_cur_g[N_GAME];
__device__ int   g_srcs_u[EMAX];
__device__ int   g_srcs_g[EMAX];
__device__ int   g_part_u[128];
__device__ int   g_part_g[128];
__device__ float g_tmpA[DDIM * DDIM];   // Wm_played @ Wout_game
__device__ float g_tmpB[DDIM * DDIM];   // Wm_rev @ Wout_user
__device__ __nv_bfloat16 g_Wub[DDIM * DDIM];  // bf16(0.125 * Wv_game @ tmpB)
__device__ __nv_bfloat16 g_Wgb[DDIM * DDIM];  // bf16(0.125 * Wv_user @ tmpA)
__device__ float g_eu[DDIM];
__device__ float g_eg[DDIM];

// ---------------- kernel 0: 64x64-tile weight GEMM pair + edge histogram ----
__global__ void k0_gemm_hist(const float* __restrict__ A0, const float* __restrict__ B0,
                             float* __restrict__ C0,
                             const float* __restrict__ A1, const float* __restrict__ B1,
                             float* __restrict__ C1,
                             const int* __restrict__ pd, const int* __restrict__ rd, int E,
                             int* __restrict__ rp_g, int* __restrict__ rp_u)
{
    if (blockIdx.z >= 2) {
        int base = ((blockIdx.z - 2) * 16 + blockIdx.y * 4 + blockIdx.x) * 256 + threadIdx.x;
        for (int i = base; i < E; i += 32 * 256) {
            atomicAdd(&rp_g[pd[i] + 1], 1);
            atomicAdd(&rp_u[rd[i] + 1], 1);
        }
        return;
    }
    const float* A = blockIdx.z ? A1 : A0;
    const float* B = blockIdx.z ? B1 : B0;
    float*       C = blockIdx.z ? C1 : C0;
    __shared__ float As[16][64];
    __shared__ float Bs[16][64];
    const int tid = threadIdx.x;
    const int tx = tid & 15, ty = tid >> 4;
    const int row0 = blockIdx.y * 64, col0 = blockIdx.x * 64;
    const int arow = tid >> 2, ac4 = (tid & 3) * 4;
    const int brow = tid >> 4, bc4 = (tid & 15) * 4;
    float acc[4][4];
#pragma unroll
    for (int i = 0; i < 4; i++)
#pragma unroll
        for (int j = 0; j < 4; j++) acc[i][j] = 0.f;

    for (int kk = 0; kk < 256; kk += 16) {
        float4 av = *(const float4*)(A + (size_t)(row0 + arow) * 256 + kk + ac4);
        As[ac4 + 0][arow] = av.x;
        As[ac4 + 1][arow] = av.y;
        As[ac4 + 2][arow] = av.z;
        As[ac4 + 3][arow] = av.w;
        float4 bv = *(const float4*)(B + (size_t)(kk + brow) * 256 + col0 + bc4);
        *(float4*)&Bs[brow][bc4] = bv;
        __syncthreads();
#pragma unroll
        for (int k = 0; k < 16; k++) {
            float4 a = *(const float4*)&As[k][ty * 4];
            float4 b = *(const float4*)&Bs[k][tx * 4];
            float ar[4] = {a.x, a.y, a.z, a.w};
            float br[4] = {b.x, b.y, b.z, b.w};
#pragma unroll
            for (int i = 0; i < 4; i++)
#pragma unroll
                for (int j = 0; j < 4; j++) acc[i][j] += ar[i] * br[j];
        }
        __syncthreads();
    }
#pragma unroll
    for (int i = 0; i < 4; i++) {
        float4 o = make_float4(acc[i][0], acc[i][1], acc[i][2], acc[i][3]);
        *(float4*)(C + (size_t)(row0 + ty * 4 + i) * 256 + col0 + tx * 4) = o;
    }
}

// ---------------- kernel 1: bf16 weight GEMM pair + fused bias combo ----------
__global__ void k1_gemmbf_combo(const float* __restrict__ A0, const float* __restrict__ B0,
                                __nv_bfloat16* __restrict__ C0,
                                const float* __restrict__ A1, const float* __restrict__ B1,
                                __nv_bfloat16* __restrict__ C1, float scale,
                                const float* __restrict__ bv0, const float* __restrict__ T0,
                                const float* __restrict__ bm0, const float* __restrict__ W0,
                                float* __restrict__ e0,
                                const float* __restrict__ bv1, const float* __restrict__ T1,
                                const float* __restrict__ bm1, const float* __restrict__ W1,
                                float* __restrict__ e1)
{
    if (blockIdx.z == 2) {
        if (blockIdx.y != 0 || blockIdx.x >= 2) return;
        const float* bv = blockIdx.x ? bv1 : bv0;
        const float* T  = blockIdx.x ? T1  : T0;
        const float* bm = blockIdx.x ? bm1 : bm0;
        const float* W  = blockIdx.x ? W1  : W0;
        float*       e  = blockIdx.x ? e1  : e0;
        int n = threadIdx.x;
        float acc = 0.f;
#pragma unroll 8
        for (int j = 0; j < 256; j++)
            acc += bv[j] * T[j * 256 + n] + bm[j] * W[j * 256 + n];
        e[n] = 0.125f * acc;
        return;
    }
    const float* A = blockIdx.z ? A1 : A0;
    const float* B = blockIdx.z ? B1 : B0;
    __nv_bfloat16* C = blockIdx.z ? C1 : C0;
    __shared__ float As[16][64];
    __shared__ float Bs[16][64];
    const int tid = threadIdx.x;
    const int tx = tid & 15, ty = tid >> 4;
    const int row0 = blockIdx.y * 64, col0 = blockIdx.x * 64;
    const int arow = tid >> 2, ac4 = (tid & 3) * 4;
    const int brow = tid >> 4, bc4 = (tid & 15) * 4;
    float acc[4][4];
#pragma unroll
    for (int i = 0; i < 4; i++)
#pragma unroll
        for (int j = 0; j < 4; j++) acc[i][j] = 0.f;

    for (int kk = 0; kk < 256; kk += 16) {
        float4 av = *(const float4*)(A + (size_t)(row0 + arow) * 256 + kk + ac4);
        As[ac4 + 0][arow] = av.x;
        As[ac4 + 1][arow] = av.y;
        As[ac4 + 2][arow] = av.z;
        As[ac4 + 3][arow] = av.w;
        float4 bv = *(const float4*)(B + (size_t)(kk + brow) * 256 + col0 + bc4);
        *(float4*)&Bs[brow][bc4] = bv;
        __syncthreads();
#pragma unroll
        for (int k = 0; k < 16; k++) {
            float4 a = *(const float4*)&As[k][ty * 4];
            float4 b = *(const float4*)&Bs[k][tx * 4];
            float ar[4] = {a.x, a.y, a.z, a.w};
            float br[4] = {b.x, b.y, b.z, b.w};
#pragma unroll
            for (int i = 0; i < 4; i++)
#pragma unroll
                for (int j = 0; j < 4; j++) acc[i][j] += ar[i] * br[j];
        }
        __syncthreads();
    }
#pragma unroll
    for (int i = 0; i < 4; i++) {
#pragma unroll
        for (int j = 0; j < 4; j++)
            C[(size_t)(row0 + ty * 4 + i) * 256 + col0 + tx * 4 + j] =
                __float2bfloat16(acc[i][j] * scale);
    }
}

// ---------------- scan kernels ----------------
__global__ void scanA(const int* __restrict__ in_u, int len_u, int* __restrict__ part_u,
                      const int* __restrict__ in_g, int len_g, int* __restrict__ part_g)
{
    const int* in  = blockIdx.y ? in_g  : in_u;
    const int len  = blockIdx.y ? len_g : len_u;
    int* part      = blockIdx.y ? part_g : part_u;
    int t = threadIdx.x;
    int idx = blockIdx.x * 1024 + t;
    int v = (idx < len) ? in[idx] : 0;
    int lane = t & 31, wid = t >> 5;
#pragma unroll
    for (int o = 16; o; o >>= 1) v += __shfl_down_sync(0xFFFFFFFFu, v, o);
    __shared__ int ws[32];
    if (lane == 0) ws[wid] = v;
    __syncthreads();
    if (wid == 0) {
        int s = ws[lane];
#pragma unroll
        for (int o = 16; o; o >>= 1) s += __shfl_down_sync(0xFFFFFFFFu, s, o);
        if (lane == 0) part[blockIdx.x] = s;
    }
}

__global__ void scanC(int* __restrict__ rp_u, int len_u, const int* __restrict__ part_u,
                      int* __restrict__ cur_u,
                      int* __restrict__ rp_g, int len_g, const int* __restrict__ part_g,
                      int* __restrict__ cur_g)
{
    int* rp         = blockIdx.y ? rp_g  : rp_u;
    const int len   = blockIdx.y ? len_g : len_u;
    const int* part = blockIdx.y ? part_g : part_u;
    int* cur        = blockIdx.y ? cur_g : cur_u;

    __shared__ int sp[128];
    int t = threadIdx.x;
    if (t < 128) sp[t] = (t < (int)gridDim.x) ? part[t] : 0;
    __syncthreads();
    int offset = 0;
    for (int j = 0; j < (int)blockIdx.x; j++) offset += sp[j];

    int idx = blockIdx.x * 1024 + t;
    int x = (idx < len) ? rp[idx] : 0;
    int lane = t & 31, wid = t >> 5;
#pragma unroll
    for (int o = 1; o < 32; o <<= 1) {
        int n = __shfl_up_sync(0xFFFFFFFFu, x, o);
        if (lane >= o) x += n;
    }
    __shared__ int wsum[32];
    if (lane == 31) wsum[wid] = x;
    __syncthreads();
    if (wid == 0) {
        int y = wsum[lane];
#pragma unroll
        for (int o = 1; o < 32; o <<= 1) {
            int n = __shfl_up_sync(0xFFFFFFFFu, y, o);
            if (lane >= o) y += n;
        }
        wsum[lane] = y;
    }
    __syncthreads();
    int incl = x + (wid > 0 ? wsum[wid - 1] : 0) + offset;
    if (idx < len) {
        rp[idx] = incl;
        if (idx < len - 1) cur[idx] = incl;
    }
}

__global__ void bin_kernel(const int* __restrict__ ps, const int* __restrict__ pd,
                           const int* __restrict__ rs, const int* __restrict__ rd, int E,
                           int* __restrict__ cur_g, int* __restrict__ srcs_g,
                           int* __restrict__ cur_u, int* __restrict__ srcs_u)
{
    int i = blockIdx.x * blockDim.x + threadIdx.x;
    if (i < E) {
        int dg = pd[i];
        int p = atomicAdd(&cur_g[dg], 1);
        srcs_g[p] = ps[i];
        int du = rd[i];
        int q = atomicAdd(&cur_u[du], 1);
        srcs_u[q] = rs[i];
    }
}

// ---------------- fused gather + MMA + epilogue (both passes, merged grid) ----
__device__ __forceinline__ uint32_t smem_u32(const void* p)
{
    return (uint32_t)__cvta_generic_to_shared(p);
}

__device__ __forceinline__ void ldsm_x4(uint32_t* r, uint32_t addr)
{
    asm volatile("ldmatrix.sync.aligned.m8n8.x4.shared.b16 {%0,%1,%2,%3}, [%4];"
                 : "=r"(r[0]), "=r"(r[1]), "=r"(r[2]), "=r"(r[3]) : "r"(addr));
}

__device__ __forceinline__ void ldsm_x4_t(uint32_t* r, uint32_t addr)
{
    asm volatile("ldmatrix.sync.aligned.m8n8.x4.trans.shared.b16 {%0,%1,%2,%3}, [%4];"
                 : "=r"(r[0]), "=r"(r[1]), "=r"(r[2]), "=r"(r[3]) : "r"(addr));
}

__device__ __forceinline__ void mma_bf16(float* c, const uint32_t* a, const uint32_t* b)
{
    asm volatile("mma.sync.aligned.m16n8k16.row.col.f32.bf16.bf16.f32 "
                 "{%0,%1,%2,%3}, {%4,%5,%6,%7}, {%8,%9}, {%0,%1,%2,%3};"
                 : "+f"(c[0]), "+f"(c[1]), "+f"(c[2]), "+f"(c[3])
                 : "r"(a[0]), "r"(a[1]), "r"(a[2]), "r"(a[3]), "r"(b[0]), "r"(b[1]));
}

// smem layout (bytes):
//   Abf : 128 rows x 264 bf16 (528B stride, conflict-free ldmatrix) = 67584
//   B   : 2 x 16 x 264 bf16                                         = 16896
//   srp : 132 ints                                                  =   528
//   onS : 128 floats                                                =   512
#define SM_B_OFF     (128 * 264 * 2)                // 67584
#define SM_SRP_OFF   (SM_B_OFF + 2 * 16 * 264 * 2)  // 84480
#define SM_ON_OFF    (SM_SRP_OFF + 132 * 4)         // 85008
#define SM_TOTAL     (SM_ON_OFF + 128 * 4)          // 85520

__global__ __launch_bounds__(512, 1)
void fused_all(const int* __restrict__ rp_u, const int* __restrict__ srcs_u,
               const int* __restrict__ rp_g, const int* __restrict__ srcs_g,
               const float* __restrict__ x_user, const float* __restrict__ x_game,
               const __nv_bfloat16* __restrict__ Wub, const __nv_bfloat16* __restrict__ Wgb,
               const float* __restrict__ eu, const float* __restrict__ eg,
               const float* __restrict__ bout_u, const float* __restrict__ bout_g,
               float* __restrict__ out)
{
    extern __shared__ char smem[];
    __nv_bfloat16* Abf = (__nv_bfloat16*)smem;
    __nv_bfloat16* Bsm = (__nv_bfloat16*)(smem + SM_B_OFF);
    int* srp   = (int*)(smem + SM_SRP_OFF);
    float* onS = (float*)(smem + SM_ON_OFF);

    const int tid = threadIdx.x;
    const int lane = tid & 31;
    const int warp = tid >> 5;

    // ---- pass selection ----
    const bool isU = (blockIdx.x < UBLK);
    const int bm0 = (isU ? blockIdx.x : blockIdx.x - UBLK) * 128;
    const int M = isU ? N_USER : N_GAME;
    const int* rowptr = isU ? rp_u : rp_g;
    const int* srcs   = isU ? srcs_u : srcs_g;
    const float* Xsrc = isU ? x_game : x_user;
    const float* Xres = isU ? x_user : x_game;
    const __nv_bfloat16* Wb = isU ? Wub : Wgb;
    const float* extra = isU ? eu : eg;
    const float* bout  = isU ? bout_u : bout_g;
    float* Outb = isU ? out : out + (size_t)N_USER * DDIM;

    // ---- stage rowptr slice + B tile 0 ----
    for (int i = tid; i < 129; i += 512) {
        int rr = bm0 + i;
        if (rr > M) rr = M;
        srp[i] = rowptr[rr];
    }
    const int brow = tid >> 5, bq = tid & 31;
    const __nv_bfloat16* bptr = Wb + (size_t)brow * 256 + bq * 8;
    {
        uint4 b0 = *(const uint4*)bptr;
        *(uint4*)(Bsm + brow * 264 + bq * 8) = b0;
    }
    __syncthreads();

    // ---- phase 1: warp-per-row gather (2-edge unrolled), bf16 -> smem A ----
#pragma unroll 1
    for (int i = 0; i < 8; i++) {
        const int rl = warp * 8 + i;
        float4 acc0 = make_float4(0.f, 0.f, 0.f, 0.f);
        float4 acc1 = make_float4(0.f, 0.f, 0.f, 0.f);
        const int beg = srp[rl], end = srp[rl + 1];
        int e = beg;
        for (; e + 1 < end; e += 2) {
            int s0 = srcs[e], s1 = srcs[e + 1];
            const float4* p0 = (const float4*)(Xsrc + (size_t)s0 * 256);
            const float4* p1 = (const float4*)(Xsrc + (size_t)s1 * 256);
            float4 u0 = p0[lane], u1 = p0[lane + 32];
            float4 w0 = p1[lane], w1 = p1[lane + 32];
            acc0.x += u0.x + w0.x; acc0.y += u0.y + w0.y;
            acc0.z += u0.z + w0.z; acc0.w += u0.w + w0.w;
            acc1.x += u1.x + w1.x; acc1.y += u1.y + w1.y;
            acc1.z += u1.z + w1.z; acc1.w += u1.w + w1.w;
        }
        if (e < end) {
            int s0 = srcs[e];
            const float4* p0 = (const float4*)(Xsrc + (size_t)s0 * 256);
            float4 u0 = p0[lane], u1 = p0[lane + 32];
            acc0.x += u0.x; acc0.y += u0.y; acc0.z += u0.z; acc0.w += u0.w;
            acc1.x += u1.x; acc1.y += u1.y; acc1.z += u1.z; acc1.w += u1.w;
        }
        const int deg = end - beg;
        const float inv = 1.0f / (float)(deg > 1 ? deg : 1);
        __nv_bfloat162 h00 = __floats2bfloat162_rn(acc0.x * inv, acc0.y * inv);
        __nv_bfloat162 h01 = __floats2bfloat162_rn(acc0.z * inv, acc0.w * inv);
        __nv_bfloat162 h10 = __floats2bfloat162_rn(acc1.x * inv, acc1.y * inv);
        __nv_bfloat162 h11 = __floats2bfloat162_rn(acc1.z * inv, acc1.w * inv);
        uint2 w0; w0.x = *(uint32_t*)&h00; w0.y = *(uint32_t*)&h01;
        uint2 w1; w1.x = *(uint32_t*)&h10; w1.y = *(uint32_t*)&h11;
        *(uint2*)(Abf + rl * 264 + lane * 4) = w0;
        *(uint2*)(Abf + rl * 264 + 128 + lane * 4) = w1;
        if (lane == 0) onS[rl] = (deg > 0) ? 1.0f : 0.0f;
    }
    __syncthreads();

    // ---- phase 2: MMA ----
    const int wm0 = (warp >> 2) * 32;
    const int wn0 = (warp & 3) * 64;

    float acc[2][8][4];
#pragma unroll
    for (int mt = 0; mt < 2; mt++)
#pragma unroll
        for (int nt = 0; nt < 8; nt++)
#pragma unroll
            for (int j = 0; j < 4; j++) acc[mt][nt][j] = 0.f;

    const uint32_t aBase = smem_u32(Abf);
    const uint32_t bBase0 = smem_u32(Bsm);
    const uint32_t bBase1 = bBase0 + 16 * 528u;

    uint4 bReg;
    for (int it = 0; it < 16; it++) {
        if (it < 15)
            bReg = *(const uint4*)(bptr + (size_t)(it + 1) * 16 * 256);

        {
            const uint32_t bB = (it & 1) ? bBase1 : bBase0;
            uint32_t ra[2][4];
#pragma unroll
            for (int mt = 0; mt < 2; mt++) {
                uint32_t addr = aBase + (uint32_t)(wm0 + mt * 16 + (lane & 15)) * 528u
                              + (uint32_t)(lane >> 4) * 16u + (uint32_t)it * 32u;
                ldsm_x4(ra[mt], addr);
            }
#pragma unroll
            for (int p = 0; p < 4; p++) {
                uint32_t rb[4];
                uint32_t addr = bB + (uint32_t)(lane & 15) * 528u
                              + (uint32_t)(wn0 + p * 16 + ((lane >> 4) * 8)) * 2u;
                ldsm_x4_t(rb, addr);
#pragma unroll
                for (int mt = 0; mt < 2; mt++) {
                    mma_bf16(acc[mt][2 * p + 0], ra[mt], rb + 0);
                    mma_bf16(acc[mt][2 * p + 1], ra[mt], rb + 2);
                }
            }
        }

        if (it < 15) {
            int nb = (it + 1) & 1;
            *(uint4*)(Bsm + nb * 16 * 264 + brow * 264 + bq * 8) = bReg;
            __syncthreads();
        }
    }

    // ---- epilogue ----
    const int groupID = lane >> 2;
    const int tig = lane & 3;
#pragma unroll
    for (int nt = 0; nt < 8; nt++) {
        const int col = wn0 + nt * 8 + tig * 2;
        const float2 bo = *(const float2*)(bout + col);
        const float2 ev = *(const float2*)(extra + col);
#pragma unroll
        for (int mt = 0; mt < 2; mt++) {
            const int lrow0 = wm0 + mt * 16 + groupID;
            const int row0 = bm0 + lrow0;
            if (row0 < M) {
                float on = onS[lrow0];
                float2 xv = *(const float2*)(Xres + (size_t)row0 * 256 + col);
                float2 o;
                o.x = fmaxf(acc[mt][nt][0] + bo.x + on * ev.x + xv.x, 0.f);
                o.y = fmaxf(acc[mt][nt][1] + bo.y + on * ev.y + xv.y, 0.f);
                *(float2*)(Outb + (size_t)row0 * 256 + col) = o;
            }
            const int lrow1 = lrow0 + 8;
            const int row1 = row0 + 8;
            if (row1 < M) {
                float on = onS[lrow1];
                float2 xv = *(const float2*)(Xres + (size_t)row1 * 256 + col);
                float2 o;
                o.x = fmaxf(acc[mt][nt][2] + bo.x + on * ev.x + xv.x, 0.f);
                o.y = fmaxf(acc[mt][nt][3] + bo.y + on * ev.y + xv.y, 0.f);
                *(float2*)(Outb + (size_t)row1 * 256 + col) = o;
            }
        }
    }
}

// ---------------- host launch ----------------
extern "C" void kernel_launch(void* const* d_in, const int* in_sizes, int n_in,
                              void* d_out, int out_size)
{
    const float* x_user    = (const float*)d_in[0];
    const float* x_game    = (const float*)d_in[1];
    const float* Wv_user   = (const float*)d_in[6];
    const float* bv_user   = (const float*)d_in[7];
    const float* Wout_user = (const float*)d_in[8];
    const float* bout_user = (const float*)d_in[9];
    const float* Wv_game   = (const float*)d_in[14];
    const float* bv_game   = (const float*)d_in[15];
    const float* Wout_game = (const float*)d_in[16];
    const float* bout_game = (const float*)d_in[17];
    const float* Wm_played = (const float*)d_in[20];
    const float* bm_played = (const float*)d_in[21];
    const float* Wm_rev    = (const float*)d_in[24];
    const float* bm_rev    = (const float*)d_in[25];
    const int* ps = (const int*)d_in[26];
    const int* pd = (const int*)d_in[27];
    const int* rs = (const int*)d_in[28];
    const int* rd = (const int*)d_in[29];
    const int E = in_sizes[26];

    float* out = (float*)d_out;

    float *tmpA, *tmpB, *eu, *eg;
    int *rp_u, *rp_g, *cur_u, *cur_g, *srcs_u, *srcs_g, *part_u, *part_g;
    __nv_bfloat16 *Wub, *Wgb;
    cudaGetSymbolAddress((void**)&rp_u,   g_rp_u);
    cudaGetSymbolAddress((void**)&rp_g,   g_rp_g);
    cudaGetSymbolAddress((void**)&cur_u,  g_cur_u);
    cudaGetSymbolAddress((void**)&cur_g,  g_cur_g);
    cudaGetSymbolAddress((void**)&srcs_u, g_srcs_u);
    cudaGetSymbolAddress((void**)&srcs_g, g_srcs_g);
    cudaGetSymbolAddress((void**)&part_u, g_part_u);
    cudaGetSymbolAddress((void**)&part_g, g_part_g);
    cudaGetSymbolAddress((void**)&tmpA,   g_tmpA);
    cudaGetSymbolAddress((void**)&tmpB,   g_tmpB);
    cudaGetSymbolAddress((void**)&Wub,    g_Wub);
    cudaGetSymbolAddress((void**)&Wgb,    g_Wgb);
    cudaGetSymbolAddress((void**)&eu,     g_eu);
    cudaGetSymbolAddress((void**)&eg,     g_eg);

    cudaFuncSetAttribute(fused_all,
                         cudaFuncAttributeMaxDynamicSharedMemorySize, SM_TOTAL);

    cudaMemsetAsync(rp_u, 0, (size_t)(N_USER + 1) * sizeof(int));
    cudaMemsetAsync(rp_g, 0, (size_t)(N_GAME + 1) * sizeof(int));

    const int len_u = N_USER + 1, len_g = N_GAME + 1;
    const int sgx = (len_u + 1023) / 1024;

    // kernel 0: weight-chain GEMM pair + histogram
    k0_gemm_hist<<<dim3(4, 4, 4), 256>>>(Wm_played, Wout_game, tmpA,
                                         Wm_rev, Wout_user, tmpB,
                                         pd, rd, E, rp_g, rp_u);
    // kernel 1: bf16 weight GEMM pair + bias combo
    k1_gemmbf_combo<<<dim3(4, 4, 3), 256>>>(Wv_user, tmpA, Wgb,
                                            Wv_game, tmpB, Wub, 0.125f,
                                            bv_user, tmpA, bm_played, Wout_game, eg,
                                            bv_game, tmpB, bm_rev, Wout_user, eu);
    // kernels 2,3: scan
    scanA<<<dim3(sgx, 2), 1024>>>(rp_u, len_u, part_u, rp_g, len_g, part_g);
    scanC<<<dim3(sgx, 2), 1024>>>(rp_u, len_u, part_u, cur_u, rp_g, len_g, part_g, cur_g);
    // kernel 4: bin edges into CSR
    bin_kernel<<<(E + 255) / 256, 256>>>(ps, pd, rs, rd, E, cur_g, srcs_g, cur_u, srcs_u);
    // kernel 5 (profiled): fused gather + MMA + epilogue, both passes
    fused_all<<<UBLK + GBLK, 512, SM_TOTAL>>>(rp_u, srcs_u, rp_g, srcs_g,
                                              x_user, x_game, Wub, Wgb,
                                              eu, eg, bout_user, bout_game, out);
}

// round 12
// speedup vs baseline: 1.3156x; 1.0195x over previous
#include <cuda_runtime.h>
#include <cuda_bf16.h>
#include <cstdint>

#define N_USER 100000
#define N_GAME 50000
#define DDIM   256
#define EMAX   200000
#define UBLK   ((N_USER + 127) / 128)   // 782
#define GBLK   ((N_GAME + 127) / 128)   // 391

// ---------------- scratch (device globals) ----------------
__device__ int   g_rp_u[N_USER + 1];
__device__ int   g_rp_g[N_GAME + 1];
__device__ int   g_cur_u[N_USER];
__device__ int   g_cur_g[N_GAME];
__device__ int   g_srcs_u[EMAX];
__device__ int   g_srcs_g[EMAX];
__device__ int   g_part_u[128];
__device__ int   g_part_g[128];
__device__ float g_tmpA[DDIM * DDIM];   // Wm_played @ Wout_game
__device__ float g_tmpB[DDIM * DDIM];   // Wm_rev @ Wout_user
__device__ __nv_bfloat16 g_Wub[DDIM * DDIM];  // bf16(0.125 * Wv_game @ tmpB)
__device__ __nv_bfloat16 g_Wgb[DDIM * DDIM];  // bf16(0.125 * Wv_user @ tmpA)
__device__ float g_eu[DDIM];
__device__ float g_eg[DDIM];
__device__ __nv_bfloat16 g_Yg[(size_t)N_USER * DDIM];  // x_user @ Wgb (messages toward games)
__device__ __nv_bfloat16 g_Yu[(size_t)N_GAME * DDIM];  // x_game @ Wub (messages toward users)

// ---------------- kernel 0: 64x64-tile weight GEMM pair + edge histogram ----
__global__ void k0_gemm_hist(const float* __restrict__ A0, const float* __restrict__ B0,
                             float* __restrict__ C0,
                             const float* __restrict__ A1, const float* __restrict__ B1,
                             float* __restrict__ C1,
                             const int* __restrict__ pd, const int* __restrict__ rd, int E,
                             int* __restrict__ rp_g, int* __restrict__ rp_u)
{
    if (blockIdx.z >= 2) {
        int base = ((blockIdx.z - 2) * 16 + blockIdx.y * 4 + blockIdx.x) * 256 + threadIdx.x;
        for (int i = base; i < E; i += 32 * 256) {
            atomicAdd(&rp_g[pd[i] + 1], 1);
            atomicAdd(&rp_u[rd[i] + 1], 1);
        }
        return;
    }
    const float* A = blockIdx.z ? A1 : A0;
    const float* B = blockIdx.z ? B1 : B0;
    float*       C = blockIdx.z ? C1 : C0;
    __shared__ float As[16][64];
    __shared__ float Bs[16][64];
    const int tid = threadIdx.x;
    const int tx = tid & 15, ty = tid >> 4;
    const int row0 = blockIdx.y * 64, col0 = blockIdx.x * 64;
    const int arow = tid >> 2, ac4 = (tid & 3) * 4;
    const int brow = tid >> 4, bc4 = (tid & 15) * 4;
    float acc[4][4];
#pragma unroll
    for (int i = 0; i < 4; i++)
#pragma unroll
        for (int j = 0; j < 4; j++) acc[i][j] = 0.f;

    for (int kk = 0; kk < 256; kk += 16) {
        float4 av = *(const float4*)(A + (size_t)(row0 + arow) * 256 + kk + ac4);
        As[ac4 + 0][arow] = av.x;
        As[ac4 + 1][arow] = av.y;
        As[ac4 + 2][arow] = av.z;
        As[ac4 + 3][arow] = av.w;
        float4 bv = *(const float4*)(B + (size_t)(kk + brow) * 256 + col0 + bc4);
        *(float4*)&Bs[brow][bc4] = bv;
        __syncthreads();
#pragma unroll
        for (int k = 0; k < 16; k++) {
            float4 a = *(const float4*)&As[k][ty * 4];
            float4 b = *(const float4*)&Bs[k][tx * 4];
            float ar[4] = {a.x, a.y, a.z, a.w};
            float br[4] = {b.x, b.y, b.z, b.w};
#pragma unroll
            for (int i = 0; i < 4; i++)
#pragma unroll
                for (int j = 0; j < 4; j++) acc[i][j] += ar[i] * br[j];
        }
        __syncthreads();
    }
#pragma unroll
    for (int i = 0; i < 4; i++) {
        float4 o = make_float4(acc[i][0], acc[i][1], acc[i][2], acc[i][3]);
        *(float4*)(C + (size_t)(row0 + ty * 4 + i) * 256 + col0 + tx * 4) = o;
    }
}

// ---------------- kernel 1: bf16 weight GEMM pair + fused bias combo ----------
__global__ void k1_gemmbf_combo(const float* __restrict__ A0, const float* __restrict__ B0,
                                __nv_bfloat16* __restrict__ C0,
                                const float* __restrict__ A1, const float* __restrict__ B1,
                                __nv_bfloat16* __restrict__ C1, float scale,
                                const float* __restrict__ bv0, const float* __restrict__ T0,
                                const float* __restrict__ bm0, const float* __restrict__ W0,
                                float* __restrict__ e0,
                                const float* __restrict__ bv1, const float* __restrict__ T1,
                                const float* __restrict__ bm1, const float* __restrict__ W1,
                                float* __restrict__ e1)
{
    if (blockIdx.z == 2) {
        if (blockIdx.y != 0 || blockIdx.x >= 2) return;
        const float* bv = blockIdx.x ? bv1 : bv0;
        const float* T  = blockIdx.x ? T1  : T0;
        const float* bm = blockIdx.x ? bm1 : bm0;
        const float* W  = blockIdx.x ? W1  : W0;
        float*       e  = blockIdx.x ? e1  : e0;
        int n = threadIdx.x;
        float acc = 0.f;
#pragma unroll 8
        for (int j = 0; j < 256; j++)
            acc += bv[j] * T[j * 256 + n] + bm[j] * W[j * 256 + n];
        e[n] = 0.125f * acc;
        return;
    }
    const float* A = blockIdx.z ? A1 : A0;
    const float* B = blockIdx.z ? B1 : B0;
    __nv_bfloat16* C = blockIdx.z ? C1 : C0;
    __shared__ float As[16][64];
    __shared__ float Bs[16][64];
    const int tid = threadIdx.x;
    const int tx = tid & 15, ty = tid >> 4;
    const int row0 = blockIdx.y * 64, col0 = blockIdx.x * 64;
    const int arow = tid >> 2, ac4 = (tid & 3) * 4;
    const int brow = tid >> 4, bc4 = (tid & 15) * 4;
    float acc[4][4];
#pragma unroll
    for (int i = 0; i < 4; i++)
#pragma unroll
        for (int j = 0; j < 4; j++) acc[i][j] = 0.f;

    for (int kk = 0; kk < 256; kk += 16) {
        float4 av = *(const float4*)(A + (size_t)(row0 + arow) * 256 + kk + ac4);
        As[ac4 + 0][arow] = av.x;
        As[ac4 + 1][arow] = av.y;
        As[ac4 + 2][arow] = av.z;
        As[ac4 + 3][arow] = av.w;
        float4 bv = *(const float4*)(B + (size_t)(kk + brow) * 256 + col0 + bc4);
        *(float4*)&Bs[brow][bc4] = bv;
        __syncthreads();
#pragma unroll
        for (int k = 0; k < 16; k++) {
            float4 a = *(const float4*)&As[k][ty * 4];
            float4 b = *(const float4*)&Bs[k][tx * 4];
            float ar[4] = {a.x, a.y, a.z, a.w};
            float br[4] = {b.x, b.y, b.z, b.w};
#pragma unroll
            for (int i = 0; i < 4; i++)
#pragma unroll
                for (int j = 0; j < 4; j++) acc[i][j] += ar[i] * br[j];
        }
        __syncthreads();
    }
#pragma unroll
    for (int i = 0; i < 4; i++) {
#pragma unroll
        for (int j = 0; j < 4; j++)
            C[(size_t)(row0 + ty * 4 + i) * 256 + col0 + tx * 4 + j] =
                __float2bfloat16(acc[i][j] * scale);
    }
}

// ---------------- scan kernels ----------------
__global__ void scanA(const int* __restrict__ in_u, int len_u, int* __restrict__ part_u,
                      const int* __restrict__ in_g, int len_g, int* __restrict__ part_g)
{
    const int* in  = blockIdx.y ? in_g  : in_u;
    const int len  = blockIdx.y ? len_g : len_u;
    int* part      = blockIdx.y ? part_g : part_u;
    int t = threadIdx.x;
    int idx = blockIdx.x * 1024 + t;
    int v = (idx < len) ? in[idx] : 0;
    int lane = t & 31, wid = t >> 5;
#pragma unroll
    for (int o = 16; o; o >>= 1) v += __shfl_down_sync(0xFFFFFFFFu, v, o);
    __shared__ int ws[32];
    if (lane == 0) ws[wid] = v;
    __syncthreads();
    if (wid == 0) {
        int s = ws[lane];
#pragma unroll
        for (int o = 16; o; o >>= 1) s += __shfl_down_sync(0xFFFFFFFFu, s, o);
        if (lane == 0) part[blockIdx.x] = s;
    }
}

__global__ void scanC(int* __restrict__ rp_u, int len_u, const int* __restrict__ part_u,
                      int* __restrict__ cur_u,
                      int* __restrict__ rp_g, int len_g, const int* __restrict__ part_g,
                      int* __restrict__ cur_g)
{
    int* rp         = blockIdx.y ? rp_g  : rp_u;
    const int len   = blockIdx.y ? len_g : len_u;
    const int* part = blockIdx.y ? part_g : part_u;
    int* cur        = blockIdx.y ? cur_g : cur_u;

    __shared__ int sp[128];
    int t = threadIdx.x;
    if (t < 128) sp[t] = (t < (int)gridDim.x) ? part[t] : 0;
    __syncthreads();
    int offset = 0;
    for (int j = 0; j < (int)blockIdx.x; j++) offset += sp[j];

    int idx = blockIdx.x * 1024 + t;
    int x = (idx < len) ? rp[idx] : 0;
    int lane = t & 31, wid = t >> 5;
#pragma unroll
    for (int o = 1; o < 32; o <<= 1) {
        int n = __shfl_up_sync(0xFFFFFFFFu, x, o);
        if (lane >= o) x += n;
    }
    __shared__ int wsum[32];
    if (lane == 31) wsum[wid] = x;
    __syncthreads();
    if (wid == 0) {
        int y = wsum[lane];
#pragma unroll
        for (int o = 1; o < 32; o <<= 1) {
            int n = __shfl_up_sync(0xFFFFFFFFu, y, o);
            if (lane >= o) y += n;
        }
        wsum[lane] = y;
    }
    __syncthreads();
    int incl = x + (wid > 0 ? wsum[wid - 1] : 0) + offset;
    if (idx < len) {
        rp[idx] = incl;
        if (idx < len - 1) cur[idx] = incl;
    }
}

__global__ void bin_kernel(const int* __restrict__ ps, const int* __restrict__ pd,
                           const int* __restrict__ rs, const int* __restrict__ rd, int E,
                           int* __restrict__ cur_g, int* __restrict__ srcs_g,
                           int* __restrict__ cur_u, int* __restrict__ srcs_u)
{
    int i = blockIdx.x * blockDim.x + threadIdx.x;
    if (i < E) {
        int dg = pd[i];
        int p = atomicAdd(&cur_g[dg], 1);
        srcs_g[p] = ps[i];
        int du = rd[i];
        int q = atomicAdd(&cur_u[du], 1);
        srcs_u[q] = rs[i];
    }
}

// ---------------- MMA helpers ----------------
__device__ __forceinline__ uint32_t smem_u32(const void* p)
{
    return (uint32_t)__cvta_generic_to_shared(p);
}

__device__ __forceinline__ void ldsm_x4(uint32_t* r, uint32_t addr)
{
    asm volatile("ldmatrix.sync.aligned.m8n8.x4.shared.b16 {%0,%1,%2,%3}, [%4];"
                 : "=r"(r[0]), "=r"(r[1]), "=r"(r[2]), "=r"(r[3]) : "r"(addr));
}

__device__ __forceinline__ void ldsm_x4_t(uint32_t* r, uint32_t addr)
{
    asm volatile("ldmatrix.sync.aligned.m8n8.x4.trans.shared.b16 {%0,%1,%2,%3}, [%4];"
                 : "=r"(r[0]), "=r"(r[1]), "=r"(r[2]), "=r"(r[3]) : "r"(addr));
}

__device__ __forceinline__ void mma_bf16(float* c, const uint32_t* a, const uint32_t* b)
{
    asm volatile("mma.sync.aligned.m16n8k16.row.col.f32.bf16.bf16.f32 "
                 "{%0,%1,%2,%3}, {%4,%5,%6,%7}, {%8,%9}, {%0,%1,%2,%3};"
                 : "+f"(c[0]), "+f"(c[1]), "+f"(c[2]), "+f"(c[3])
                 : "r"(a[0]), "r"(a[1]), "r"(a[2]), "r"(a[3]), "r"(b[0]), "r"(b[1]));
}

// ---------------- gemmY: dense streaming GEMM Y = bf16(X @ Wb) ----------------
// smem: Abf 128x264 bf16 (67584) + B 2x16x264 bf16 (16896) = 84480
#define SMY_B_OFF  (128 * 264 * 2)
#define SMY_TOTAL  (SMY_B_OFF + 2 * 16 * 264 * 2)

__global__ __launch_bounds__(512, 1)
void gemmY(const float* __restrict__ x_user, const float* __restrict__ x_game,
           const __nv_bfloat16* __restrict__ Wgb, const __nv_bfloat16* __restrict__ Wub,
           __nv_bfloat16* __restrict__ Yg, __nv_bfloat16* __restrict__ Yu)
{
    extern __shared__ char smem[];
    __nv_bfloat16* Abf = (__nv_bfloat16*)smem;
    __nv_bfloat16* Bsm = (__nv_bfloat16*)(smem + SMY_B_OFF);

    const int tid = threadIdx.x;
    const int lane = tid & 31;
    const int warp = tid >> 5;

    const bool isU = (blockIdx.x < UBLK);   // user rows -> Yg
    const int bm0 = (isU ? blockIdx.x : blockIdx.x - UBLK) * 128;
    const int M = isU ? N_USER : N_GAME;
    const float* X = isU ? x_user : x_game;
    const __nv_bfloat16* Wb = isU ? Wgb : Wub;
    __nv_bfloat16* Y = isU ? Yg : Yu;

    // stage B tile 0
    const int brow = tid >> 5, bq = tid & 31;
    const __nv_bfloat16* bptr = Wb + (size_t)brow * 256 + bq * 8;
    {
        uint4 b0 = *(const uint4*)bptr;
        *(uint4*)(Bsm + brow * 264 + bq * 8) = b0;
    }

    // phase 1: streaming A load + bf16 convert
    const float4* X4 = (const float4*)X;
#pragma unroll
    for (int i = 0; i < 8; i++) {
        const int rl = warp * 8 + i;
        const int r = bm0 + rl;
        float4 a0 = make_float4(0.f, 0.f, 0.f, 0.f);
        float4 a1 = make_float4(0.f, 0.f, 0.f, 0.f);
        if (r < M) {
            a0 = X4[(size_t)r * 64 + lane];
            a1 = X4[(size_t)r * 64 + 32 + lane];
        }
        __nv_bfloat162 h00 = __floats2bfloat162_rn(a0.x, a0.y);
        __nv_bfloat162 h01 = __floats2bfloat162_rn(a0.z, a0.w);
        __nv_bfloat162 h10 = __floats2bfloat162_rn(a1.x, a1.y);
        __nv_bfloat162 h11 = __floats2bfloat162_rn(a1.z, a1.w);
        uint2 w0; w0.x = *(uint32_t*)&h00; w0.y = *(uint32_t*)&h01;
        uint2 w1; w1.x = *(uint32_t*)&h10; w1.y = *(uint32_t*)&h11;
        *(uint2*)(Abf + rl * 264 + lane * 4) = w0;
        *(uint2*)(Abf + rl * 264 + 128 + lane * 4) = w1;
    }
    __syncthreads();

    // phase 2: MMA
    const int wm0 = (warp >> 2) * 32;
    const int wn0 = (warp & 3) * 64;

    float acc[2][8][4];
#pragma unroll
    for (int mt = 0; mt < 2; mt++)
#pragma unroll
        for (int nt = 0; nt < 8; nt++)
#pragma unroll
            for (int j = 0; j < 4; j++) acc[mt][nt][j] = 0.f;

    const uint32_t aBase = smem_u32(Abf);
    const uint32_t bBase0 = smem_u32(Bsm);
    const uint32_t bBase1 = bBase0 + 16 * 528u;

    uint4 bReg;
    for (int it = 0; it < 16; it++) {
        if (it < 15)
            bReg = *(const uint4*)(bptr + (size_t)(it + 1) * 16 * 256);
        {
            const uint32_t bB = (it & 1) ? bBase1 : bBase0;
            uint32_t ra[2][4];
#pragma unroll
            for (int mt = 0; mt < 2; mt++) {
                uint32_t addr = aBase + (uint32_t)(wm0 + mt * 16 + (lane & 15)) * 528u
                              + (uint32_t)(lane >> 4) * 16u + (uint32_t)it * 32u;
                ldsm_x4(ra[mt], addr);
            }
#pragma unroll
            for (int p = 0; p < 4; p++) {
                uint32_t rb[4];
                uint32_t addr = bB + (uint32_t)(lane & 15) * 528u
                              + (uint32_t)(wn0 + p * 16 + ((lane >> 4) * 8)) * 2u;
                ldsm_x4_t(rb, addr);
#pragma unroll
                for (int mt = 0; mt < 2; mt++) {
                    mma_bf16(acc[mt][2 * p + 0], ra[mt], rb + 0);
                    mma_bf16(acc[mt][2 * p + 1], ra[mt], rb + 2);
                }
            }
        }
        if (it < 15) {
            int nb = (it + 1) & 1;
            *(uint4*)(Bsm + nb * 16 * 264 + brow * 264 + bq * 8) = bReg;
            __syncthreads();
        }
    }

    // epilogue: store bf16 Y
    const int groupID = lane >> 2;
    const int tig = lane & 3;
#pragma unroll
    for (int nt = 0; nt < 8; nt++) {
        const int col = wn0 + nt * 8 + tig * 2;
#pragma unroll
        for (int mt = 0; mt < 2; mt++) {
            const int row0 = bm0 + wm0 + mt * 16 + groupID;
            if (row0 < M) {
                __nv_bfloat162 h = __floats2bfloat162_rn(acc[mt][nt][0], acc[mt][nt][1]);
                *(__nv_bfloat162*)(Y + (size_t)row0 * 256 + col) = h;
            }
            const int row1 = row0 + 8;
            if (row1 < M) {
                __nv_bfloat162 h = __floats2bfloat162_rn(acc[mt][nt][2], acc[mt][nt][3]);
                *(__nv_bfloat162*)(Y + (size_t)row1 * 256 + col) = h;
            }
        }
    }
}

// ---------------- gather_ep: warp-per-row bf16 Y gather + epilogue ----------
#define GR_ROWS 64
#define GR_UB   ((N_USER + GR_ROWS - 1) / GR_ROWS)   // 1563
#define GR_GB   ((N_GAME + GR_ROWS - 1) / GR_ROWS)   // 782

__global__ __launch_bounds__(256)
void gather_ep(const int* __restrict__ rp_u, const int* __restrict__ srcs_u,
               const int* __restrict__ rp_g, const int* __restrict__ srcs_g,
               const __nv_bfloat16* __restrict__ Yu, const __nv_bfloat16* __restrict__ Yg,
               const float* __restrict__ x_user, const float* __restrict__ x_game,
               const float* __restrict__ eu, const float* __restrict__ eg,
               const float* __restrict__ bout_u, const float* __restrict__ bout_g,
               float* __restrict__ out)
{
    const int lane = threadIdx.x & 31;
    const int warp = threadIdx.x >> 5;

    const bool isU = (blockIdx.x < GR_UB);
    const int r0 = (isU ? blockIdx.x : blockIdx.x - GR_UB) * GR_ROWS;
    const int M = isU ? N_USER : N_GAME;
    const int* rowptr = isU ? rp_u : rp_g;
    const int* srcs   = isU ? srcs_u : srcs_g;
    const uint4* Y4   = (const uint4*)(isU ? Yu : Yg);
    const float* Xres = isU ? x_user : x_game;
    const float* extra = isU ? eu : eg;
    const float* bout  = isU ? bout_u : bout_g;
    float* Outb = isU ? out : out + (size_t)N_USER * DDIM;

    // per-lane bias registers for cols lane*8 .. lane*8+7
    const float4 bo0 = *(const float4*)(bout + lane * 8);
    const float4 bo1 = *(const float4*)(bout + lane * 8 + 4);
    const float4 ev0 = *(const float4*)(extra + lane * 8);
    const float4 ev1 = *(const float4*)(extra + lane * 8 + 4);

    const int rend = (r0 + GR_ROWS < M) ? r0 + GR_ROWS : M;
#pragma unroll 1
    for (int r = r0 + warp; r < rend; r += 8) {
        const int beg = __ldg(rowptr + r);
        const int end = __ldg(rowptr + r + 1);
        float acc[8];
#pragma unroll
        for (int j = 0; j < 8; j++) acc[j] = 0.f;

        int e = beg;
        for (; e + 1 < end; e += 2) {
            int s0 = __ldg(srcs + e), s1 = __ldg(srcs + e + 1);
            uint4 v0 = Y4[(size_t)s0 * 32 + lane];
            uint4 v1 = Y4[(size_t)s1 * 32 + lane];
            float2 f;
            f = __bfloat1622float2(*(__nv_bfloat162*)&v0.x); acc[0] += f.x; acc[1] += f.y;
            f = __bfloat1622float2(*(__nv_bfloat162*)&v0.y); acc[2] += f.x; acc[3] += f.y;
            f = __bfloat1622float2(*(__nv_bfloat162*)&v0.z); acc[4] += f.x; acc[5] += f.y;
            f = __bfloat1622float2(*(__nv_bfloat162*)&v0.w); acc[6] += f.x; acc[7] += f.y;
            f = __bfloat1622float2(*(__nv_bfloat162*)&v1.x); acc[0] += f.x; acc[1] += f.y;
            f = __bfloat1622float2(*(__nv_bfloat162*)&v1.y); acc[2] += f.x; acc[3] += f.y;
            f = __bfloat1622float2(*(__nv_bfloat162*)&v1.z); acc[4] += f.x; acc[5] += f.y;
            f = __bfloat1622float2(*(__nv_bfloat162*)&v1.w); acc[6] += f.x; acc[7] += f.y;
        }
        if (e < end) {
            int s0 = __ldg(srcs + e);
            uint4 v0 = Y4[(size_t)s0 * 32 + lane];
            float2 f;
            f = __bfloat1622float2(*(__nv_bfloat162*)&v0.x); acc[0] += f.x; acc[1] += f.y;
            f = __bfloat1622float2(*(__nv_bfloat162*)&v0.y); acc[2] += f.x; acc[3] += f.y;
            f = __bfloat1622float2(*(__nv_bfloat162*)&v0.z); acc[4] += f.x; acc[5] += f.y;
            f = __bfloat1622float2(*(__nv_bfloat162*)&v0.w); acc[6] += f.x; acc[7] += f.y;
        }

        const int deg = end - beg;
        const float inv = 1.0f / (float)(deg > 1 ? deg : 1);
        const float on = (deg > 0) ? 1.0f : 0.0f;
        const float4 x0 = *(const float4*)(Xres + (size_t)r * 256 + lane * 8);
        const float4 x1 = *(const float4*)(Xres + (size_t)r * 256 + lane * 8 + 4);
        float4 o0, o1;
        o0.x = fmaxf(acc[0] * inv + bo0.x + on * ev0.x + x0.x, 0.f);
        o0.y = fmaxf(acc[1] * inv + bo0.y + on * ev0.y + x0.y, 0.f);
        o0.z = fmaxf(acc[2] * inv + bo0.z + on * ev0.z + x0.z, 0.f);
        o0.w = fmaxf(acc[3] * inv + bo0.w + on * ev0.w + x0.w, 0.f);
        o1.x = fmaxf(acc[4] * inv + bo1.x + on * ev1.x + x1.x, 0.f);
        o1.y = fmaxf(acc[5] * inv + bo1.y + on * ev1.y + x1.y, 0.f);
        o1.z = fmaxf(acc[6] * inv + bo1.z + on * ev1.z + x1.z, 0.f);
        o1.w = fmaxf(acc[7] * inv + bo1.w + on * ev1.w + x1.w, 0.f);
        *(float4*)(Outb + (size_t)r * 256 + lane * 8) = o0;
        *(float4*)(Outb + (size_t)r * 256 + lane * 8 + 4) = o1;
    }
}

// ---------------- host launch ----------------
extern "C" void kernel_launch(void* const* d_in, const int* in_sizes, int n_in,
                              void* d_out, int out_size)
{
    const float* x_user    = (const float*)d_in[0];
    const float* x_game    = (const float*)d_in[1];
    const float* Wv_user   = (const float*)d_in[6];
    const float* bv_user   = (const float*)d_in[7];
    const float* Wout_user = (const float*)d_in[8];
    const float* bout_user = (const float*)d_in[9];
    const float* Wv_game   = (const float*)d_in[14];
    const float* bv_game   = (const float*)d_in[15];
    const float* Wout_game = (const float*)d_in[16];
    const float* bout_game = (const float*)d_in[17];
    const float* Wm_played = (const float*)d_in[20];
    const float* bm_played = (const float*)d_in[21];
    const float* Wm_rev    = (const float*)d_in[24];
    const float* bm_rev    = (const float*)d_in[25];
    const int* ps = (const int*)d_in[26];
    const int* pd = (const int*)d_in[27];
    const int* rs = (const int*)d_in[28];
    const int* rd = (const int*)d_in[29];
    const int E = in_sizes[26];

    float* out = (float*)d_out;

    float *tmpA, *tmpB, *eu, *eg;
    int *rp_u, *rp_g, *cur_u, *cur_g, *srcs_u, *srcs_g, *part_u, *part_g;
    __nv_bfloat16 *Wub, *Wgb, *Yg, *Yu;
    cudaGetSymbolAddress((void**)&rp_u,   g_rp_u);
    cudaGetSymbolAddress((void**)&rp_g,   g_rp_g);
    cudaGetSymbolAddress((void**)&cur_u,  g_cur_u);
    cudaGetSymbolAddress((void**)&cur_g,  g_cur_g);
    cudaGetSymbolAddress((void**)&srcs_u, g_srcs_u);
    cudaGetSymbolAddress((void**)&srcs_g, g_srcs_g);
    cudaGetSymbolAddress((void**)&part_u, g_part_u);
    cudaGetSymbolAddress((void**)&part_g, g_part_g);
    cudaGetSymbolAddress((void**)&tmpA,   g_tmpA);
    cudaGetSymbolAddress((void**)&tmpB,   g_tmpB);
    cudaGetSymbolAddress((void**)&Wub,    g_Wub);
    cudaGetSymbolAddress((void**)&Wgb,    g_Wgb);
    cudaGetSymbolAddress((void**)&eu,     g_eu);
    cudaGetSymbolAddress((void**)&eg,     g_eg);
    cudaGetSymbolAddress((void**)&Yg,     g_Yg);
    cudaGetSymbolAddress((void**)&Yu,     g_Yu);

    cudaFuncSetAttribute(gemmY,
                         cudaFuncAttributeMaxDynamicSharedMemorySize, SMY_TOTAL);

    cudaMemsetAsync(rp_u, 0, (size_t)(N_USER + 1) * sizeof(int));
    cudaMemsetAsync(rp_g, 0, (size_t)(N_GAME + 1) * sizeof(int));

    const int len_u = N_USER + 1, len_g = N_GAME + 1;
    const int sgx = (len_u + 1023) / 1024;

    // launch idx 2: weight-chain GEMM pair + histogram
    k0_gemm_hist<<<dim3(4, 4, 4), 256>>>(Wm_played, Wout_game, tmpA,
                                         Wm_rev, Wout_user, tmpB,
                                         pd, rd, E, rp_g, rp_u);
    // idx 3: bf16 weight GEMM pair + bias combo
    k1_gemmbf_combo<<<dim3(4, 4, 3), 256>>>(Wv_user, tmpA, Wgb,
                                            Wv_game, tmpB, Wub, 0.125f,
                                            bv_user, tmpA, bm_played, Wout_game, eg,
                                            bv_game, tmpB, bm_rev, Wout_user, eu);
    // idx 4: scan partials
    scanA<<<dim3(sgx, 2), 1024>>>(rp_u, len_u, part_u, rp_g, len_g, part_g);
    // idx 5 (profiled): dense streaming GEMM Y = bf16(X @ Wcombined)
    gemmY<<<UBLK + GBLK, 512, SMY_TOTAL>>>(x_user, x_game, Wgb, Wub, Yg, Yu);
    // idx 6: finish scan + cursor init
    scanC<<<dim3(sgx, 2), 1024>>>(rp_u, len_u, part_u, cur_u, rp_g, len_g, part_g, cur_g);
    // idx 7: bin edges into CSR
    bin_kernel<<<(E + 255) / 256, 256>>>(ps, pd, rs, rd, E, cur_g, srcs_g, cur_u, srcs_u);
    // idx 8: bf16 gather + epilogue
    gather_ep<<<GR_UB + GR_GB, 256>>>(rp_u, srcs_u, rp_g, srcs_g, Yu, Yg,
                                      x_user, x_game, eu, eg,
                                      bout_user, bout_game, out);
}

// round 13
// speedup vs baseline: 1.3246x; 1.0069x over previous
#include <cuda_runtime.h>
#include <cuda_bf16.h>
#include <cstdint>

#define N_USER 100000
#define N_GAME 50000
#define DDIM   256
#define EMAX   200000

// ---------------- scratch (device globals) ----------------
__device__ int   g_rp_u[N_USER + 1];
__device__ int   g_rp_g[N_GAME + 1];
__device__ int   g_cur_u[N_USER];
__device__ int   g_cur_g[N_GAME];
__device__ int   g_srcs_u[EMAX];
__device__ int   g_srcs_g[EMAX];
__device__ int   g_part_u[128];
__device__ int   g_part_g[128];
__device__ float g_tmpA[DDIM * DDIM];   // Wm_played @ Wout_game
__device__ float g_tmpB[DDIM * DDIM];   // Wm_rev @ Wout_user
__device__ __nv_bfloat16 g_Wub[DDIM * DDIM];  // bf16(0.125 * Wv_game @ tmpB)
__device__ __nv_bfloat16 g_Wgb[DDIM * DDIM];  // bf16(0.125 * Wv_user @ tmpA)
__device__ float g_eu[DDIM];
__device__ float g_eg[DDIM];
__device__ __nv_bfloat16 g_Yg[(size_t)N_USER * DDIM];  // x_user @ Wgb
__device__ __nv_bfloat16 g_Yu[(size_t)N_GAME * DDIM];  // x_game @ Wub

// ---------------- kernel 0: 64x64-tile weight GEMM pair + edge histogram ----
__global__ void k0_gemm_hist(const float* __restrict__ A0, const float* __restrict__ B0,
                             float* __restrict__ C0,
                             const float* __restrict__ A1, const float* __restrict__ B1,
                             float* __restrict__ C1,
                             const int* __restrict__ pd, const int* __restrict__ rd, int E,
                             int* __restrict__ rp_g, int* __restrict__ rp_u)
{
    if (blockIdx.z >= 2) {
        int base = ((blockIdx.z - 2) * 16 + blockIdx.y * 4 + blockIdx.x) * 256 + threadIdx.x;
        for (int i = base; i < E; i += 32 * 256) {
            atomicAdd(&rp_g[pd[i] + 1], 1);
            atomicAdd(&rp_u[rd[i] + 1], 1);
        }
        return;
    }
    const float* A = blockIdx.z ? A1 : A0;
    const float* B = blockIdx.z ? B1 : B0;
    float*       C = blockIdx.z ? C1 : C0;
    __shared__ float As[16][64];
    __shared__ float Bs[16][64];
    const int tid = threadIdx.x;
    const int tx = tid & 15, ty = tid >> 4;
    const int row0 = blockIdx.y * 64, col0 = blockIdx.x * 64;
    const int arow = tid >> 2, ac4 = (tid & 3) * 4;
    const int brow = tid >> 4, bc4 = (tid & 15) * 4;
    float acc[4][4];
#pragma unroll
    for (int i = 0; i < 4; i++)
#pragma unroll
        for (int j = 0; j < 4; j++) acc[i][j] = 0.f;

    for (int kk = 0; kk < 256; kk += 16) {
        float4 av = *(const float4*)(A + (size_t)(row0 + arow) * 256 + kk + ac4);
        As[ac4 + 0][arow] = av.x;
        As[ac4 + 1][arow] = av.y;
        As[ac4 + 2][arow] = av.z;
        As[ac4 + 3][arow] = av.w;
        float4 bv = *(const float4*)(B + (size_t)(kk + brow) * 256 + col0 + bc4);
        *(float4*)&Bs[brow][bc4] = bv;
        __syncthreads();
#pragma unroll
        for (int k = 0; k < 16; k++) {
            float4 a = *(const float4*)&As[k][ty * 4];
            float4 b = *(const float4*)&Bs[k][tx * 4];
            float ar[4] = {a.x, a.y, a.z, a.w};
            float br[4] = {b.x, b.y, b.z, b.w};
#pragma unroll
            for (int i = 0; i < 4; i++)
#pragma unroll
                for (int j = 0; j < 4; j++) acc[i][j] += ar[i] * br[j];
        }
        __syncthreads();
    }
#pragma unroll
    for (int i = 0; i < 4; i++) {
        float4 o = make_float4(acc[i][0], acc[i][1], acc[i][2], acc[i][3]);
        *(float4*)(C + (size_t)(row0 + ty * 4 + i) * 256 + col0 + tx * 4) = o;
    }
}

// ---------------- kernel 1: bf16 weight GEMM pair + fused bias combo ----------
__global__ void k1_gemmbf_combo(const float* __restrict__ A0, const float* __restrict__ B0,
                                __nv_bfloat16* __restrict__ C0,
                                const float* __restrict__ A1, const float* __restrict__ B1,
                                __nv_bfloat16* __restrict__ C1, float scale,
                                const float* __restrict__ bv0, const float* __restrict__ T0,
                                const float* __restrict__ bm0, const float* __restrict__ W0,
                                float* __restrict__ e0,
                                const float* __restrict__ bv1, const float* __restrict__ T1,
                                const float* __restrict__ bm1, const float* __restrict__ W1,
                                float* __restrict__ e1)
{
    if (blockIdx.z == 2) {
        if (blockIdx.y != 0 || blockIdx.x >= 2) return;
        const float* bv = blockIdx.x ? bv1 : bv0;
        const float* T  = blockIdx.x ? T1  : T0;
        const float* bm = blockIdx.x ? bm1 : bm0;
        const float* W  = blockIdx.x ? W1  : W0;
        float*       e  = blockIdx.x ? e1  : e0;
        int n = threadIdx.x;
        float acc = 0.f;
#pragma unroll 8
        for (int j = 0; j < 256; j++)
            acc += bv[j] * T[j * 256 + n] + bm[j] * W[j * 256 + n];
        e[n] = 0.125f * acc;
        return;
    }
    const float* A = blockIdx.z ? A1 : A0;
    const float* B = blockIdx.z ? B1 : B0;
    __nv_bfloat16* C = blockIdx.z ? C1 : C0;
    __shared__ float As[16][64];
    __shared__ float Bs[16][64];
    const int tid = threadIdx.x;
    const int tx = tid & 15, ty = tid >> 4;
    const int row0 = blockIdx.y * 64, col0 = blockIdx.x * 64;
    const int arow = tid >> 2, ac4 = (tid & 3) * 4;
    const int brow = tid >> 4, bc4 = (tid & 15) * 4;
    float acc[4][4];
#pragma unroll
    for (int i = 0; i < 4; i++)
#pragma unroll
        for (int j = 0; j < 4; j++) acc[i][j] = 0.f;

    for (int kk = 0; kk < 256; kk += 16) {
        float4 av = *(const float4*)(A + (size_t)(row0 + arow) * 256 + kk + ac4);
        As[ac4 + 0][arow] = av.x;
        As[ac4 + 1][arow] = av.y;
        As[ac4 + 2][arow] = av.z;
        As[ac4 + 3][arow] = av.w;
        float4 bv = *(const float4*)(B + (size_t)(kk + brow) * 256 + col0 + bc4);
        *(float4*)&Bs[brow][bc4] = bv;
        __syncthreads();
#pragma unroll
        for (int k = 0; k < 16; k++) {
            float4 a = *(const float4*)&As[k][ty * 4];
            float4 b = *(const float4*)&Bs[k][tx * 4];
            float ar[4] = {a.x, a.y, a.z, a.w};
            float br[4] = {b.x, b.y, b.z, b.w};
#pragma unroll
            for (int i = 0; i < 4; i++)
#pragma unroll
                for (int j = 0; j < 4; j++) acc[i][j] += ar[i] * br[j];
        }
        __syncthreads();
    }
#pragma unroll
    for (int i = 0; i < 4; i++) {
#pragma unroll
        for (int j = 0; j < 4; j++)
            C[(size_t)(row0 + ty * 4 + i) * 256 + col0 + tx * 4 + j] =
                __float2bfloat16(acc[i][j] * scale);
    }
}

// ---------------- scan kernels ----------------
__global__ void scanA(const int* __restrict__ in_u, int len_u, int* __restrict__ part_u,
                      const int* __restrict__ in_g, int len_g, int* __restrict__ part_g)
{
    const int* in  = blockIdx.y ? in_g  : in_u;
    const int len  = blockIdx.y ? len_g : len_u;
    int* part      = blockIdx.y ? part_g : part_u;
    int t = threadIdx.x;
    int idx = blockIdx.x * 1024 + t;
    int v = (idx < len) ? in[idx] : 0;
    int lane = t & 31, wid = t >> 5;
#pragma unroll
    for (int o = 16; o; o >>= 1) v += __shfl_down_sync(0xFFFFFFFFu, v, o);
    __shared__ int ws[32];
    if (lane == 0) ws[wid] = v;
    __syncthreads();
    if (wid == 0) {
        int s = ws[lane];
#pragma unroll
        for (int o = 16; o; o >>= 1) s += __shfl_down_sync(0xFFFFFFFFu, s, o);
        if (lane == 0) part[blockIdx.x] = s;
    }
}

__global__ void scanC(int* __restrict__ rp_u, int len_u, const int* __restrict__ part_u,
                      int* __restrict__ cur_u,
                      int* __restrict__ rp_g, int len_g, const int* __restrict__ part_g,
                      int* __restrict__ cur_g)
{
    int* rp         = blockIdx.y ? rp_g  : rp_u;
    const int len   = blockIdx.y ? len_g : len_u;
    const int* part = blockIdx.y ? part_g : part_u;
    int* cur        = blockIdx.y ? cur_g : cur_u;

    __shared__ int sp[128];
    int t = threadIdx.x;
    if (t < 128) sp[t] = (t < (int)gridDim.x) ? part[t] : 0;
    __syncthreads();
    int offset = 0;
    for (int j = 0; j < (int)blockIdx.x; j++) offset += sp[j];

    int idx = blockIdx.x * 1024 + t;
    int x = (idx < len) ? rp[idx] : 0;
    int lane = t & 31, wid = t >> 5;
#pragma unroll
    for (int o = 1; o < 32; o <<= 1) {
        int n = __shfl_up_sync(0xFFFFFFFFu, x, o);
        if (lane >= o) x += n;
    }
    __shared__ int wsum[32];
    if (lane == 31) wsum[wid] = x;
    __syncthreads();
    if (wid == 0) {
        int y = wsum[lane];
#pragma unroll
        for (int o = 1; o < 32; o <<= 1) {
            int n = __shfl_up_sync(0xFFFFFFFFu, y, o);
            if (lane >= o) y += n;
        }
        wsum[lane] = y;
    }
    __syncthreads();
    int incl = x + (wid > 0 ? wsum[wid - 1] : 0) + offset;
    if (idx < len) {
        rp[idx] = incl;
        if (idx < len - 1) cur[idx] = incl;
    }
}

__global__ void bin_kernel(const int* __restrict__ ps, const int* __restrict__ pd,
                           const int* __restrict__ rs, const int* __restrict__ rd, int E,
                           int* __restrict__ cur_g, int* __restrict__ srcs_g,
                           int* __restrict__ cur_u, int* __restrict__ srcs_u)
{
    int i = blockIdx.x * blockDim.x + threadIdx.x;
    if (i < E) {
        int dg = pd[i];
        int p = atomicAdd(&cur_g[dg], 1);
        srcs_g[p] = ps[i];
        int du = rd[i];
        int q = atomicAdd(&cur_u[du], 1);
        srcs_u[q] = rs[i];
    }
}

// ---------------- MMA helpers ----------------
__device__ __forceinline__ uint32_t smem_u32(const void* p)
{
    return (uint32_t)__cvta_generic_to_shared(p);
}

__device__ __forceinline__ void ldsm_x4(uint32_t* r, uint32_t addr)
{
    asm volatile("ldmatrix.sync.aligned.m8n8.x4.shared.b16 {%0,%1,%2,%3}, [%4];"
                 : "=r"(r[0]), "=r"(r[1]), "=r"(r[2]), "=r"(r[3]) : "r"(addr));
}

__device__ __forceinline__ void ldsm_x4_t(uint32_t* r, uint32_t addr)
{
    asm volatile("ldmatrix.sync.aligned.m8n8.x4.trans.shared.b16 {%0,%1,%2,%3}, [%4];"
                 : "=r"(r[0]), "=r"(r[1]), "=r"(r[2]), "=r"(r[3]) : "r"(addr));
}

__device__ __forceinline__ void mma_bf16(float* c, const uint32_t* a, const uint32_t* b)
{
    asm volatile("mma.sync.aligned.m16n8k16.row.col.f32.bf16.bf16.f32 "
                 "{%0,%1,%2,%3}, {%4,%5,%6,%7}, {%8,%9}, {%0,%1,%2,%3};"
                 : "+f"(c[0]), "+f"(c[1]), "+f"(c[2]), "+f"(c[3])
                 : "r"(a[0]), "r"(a[1]), "r"(a[2]), "r"(a[3]), "r"(b[0]), "r"(b[1]));
}

// ---------------- gemmY: dense streaming GEMM Y = bf16(X @ Wb) ----------------
// v2: M=64 x N=256 tiles, 256 threads (8 warps = 2M x 4N), 2 CTAs/SM.
// smem: Abf 64x264 bf16 (33792) + B 2x16x264 bf16 (16896) = 50688
#define Y_UB   ((N_USER + 63) / 64)   // 1563
#define Y_GB   ((N_GAME + 63) / 64)   // 782
#define SMY_B_OFF  (64 * 264 * 2)
#define SMY_TOTAL  (SMY_B_OFF + 2 * 16 * 264 * 2)

__global__ __launch_bounds__(256, 2)
void gemmY(const float* __restrict__ x_user, const float* __restrict__ x_game,
           const __nv_bfloat16* __restrict__ Wgb, const __nv_bfloat16* __restrict__ Wub,
           __nv_bfloat16* __restrict__ Yg, __nv_bfloat16* __restrict__ Yu)
{
    extern __shared__ char smem[];
    __nv_bfloat16* Abf = (__nv_bfloat16*)smem;
    __nv_bfloat16* Bsm = (__nv_bfloat16*)(smem + SMY_B_OFF);

    const int tid = threadIdx.x;
    const int lane = tid & 31;
    const int warp = tid >> 5;

    const bool isU = (blockIdx.x < Y_UB);
    const int bm0 = (isU ? blockIdx.x : blockIdx.x - Y_UB) * 64;
    const int M = isU ? N_USER : N_GAME;
    const float* X = isU ? x_user : x_game;
    const __nv_bfloat16* Wb = isU ? Wgb : Wub;
    __nv_bfloat16* Y = isU ? Yg : Yu;

    // stage B tile 0: 16 rows x 256 cols bf16; 256 threads load 2 uint4 each
    const int brow = tid >> 5;          // 0..7
    const int bq = tid & 31;            // 0..31
    const __nv_bfloat16* bptr0 = Wb + (size_t)brow * 256 + bq * 8;
    const __nv_bfloat16* bptr1 = Wb + (size_t)(brow + 8) * 256 + bq * 8;
    {
        uint4 b0 = *(const uint4*)bptr0;
        uint4 b1 = *(const uint4*)bptr1;
        *(uint4*)(Bsm + brow * 264 + bq * 8) = b0;
        *(uint4*)(Bsm + (brow + 8) * 264 + bq * 8) = b1;
    }

    // phase 1: streaming A load + bf16 convert (8 rows per warp)
    const float4* X4 = (const float4*)X;
#pragma unroll
    for (int i = 0; i < 8; i++) {
        const int rl = warp * 8 + i;
        const int r = bm0 + rl;
        float4 a0 = make_float4(0.f, 0.f, 0.f, 0.f);
        float4 a1 = make_float4(0.f, 0.f, 0.f, 0.f);
        if (r < M) {
            a0 = X4[(size_t)r * 64 + lane];
            a1 = X4[(size_t)r * 64 + 32 + lane];
        }
        __nv_bfloat162 h00 = __floats2bfloat162_rn(a0.x, a0.y);
        __nv_bfloat162 h01 = __floats2bfloat162_rn(a0.z, a0.w);
        __nv_bfloat162 h10 = __floats2bfloat162_rn(a1.x, a1.y);
        __nv_bfloat162 h11 = __floats2bfloat162_rn(a1.z, a1.w);
        uint2 w0; w0.x = *(uint32_t*)&h00; w0.y = *(uint32_t*)&h01;
        uint2 w1; w1.x = *(uint32_t*)&h10; w1.y = *(uint32_t*)&h11;
        *(uint2*)(Abf + rl * 264 + lane * 4) = w0;
        *(uint2*)(Abf + rl * 264 + 128 + lane * 4) = w1;
    }
    __syncthreads();

    // phase 2: MMA. warp tile 32 (M) x 64 (N)
    const int wm0 = (warp >> 2) * 32;   // 0,32
    const int wn0 = (warp & 3) * 64;    // 0,64,128,192

    float acc[2][8][4];
#pragma unroll
    for (int mt = 0; mt < 2; mt++)
#pragma unroll
        for (int nt = 0; nt < 8; nt++)
#pragma unroll
            for (int j = 0; j < 4; j++) acc[mt][nt][j] = 0.f;

    const uint32_t aBase = smem_u32(Abf);
    const uint32_t bBase0 = smem_u32(Bsm);
    const uint32_t bBase1 = bBase0 + 16 * 528u;

    uint4 bReg0, bReg1;
    for (int it = 0; it < 16; it++) {
        if (it < 15) {
            bReg0 = *(const uint4*)(bptr0 + (size_t)(it + 1) * 16 * 256);
            bReg1 = *(const uint4*)(bptr1 + (size_t)(it + 1) * 16 * 256);
        }
        {
            const uint32_t bB = (it & 1) ? bBase1 : bBase0;
            uint32_t ra[2][4];
#pragma unroll
            for (int mt = 0; mt < 2; mt++) {
                uint32_t addr = aBase + (uint32_t)(wm0 + mt * 16 + (lane & 15)) * 528u
                              + (uint32_t)(lane >> 4) * 16u + (uint32_t)it * 32u;
                ldsm_x4(ra[mt], addr);
            }
#pragma unroll
            for (int p = 0; p < 4; p++) {
                uint32_t rb[4];
                uint32_t addr = bB + (uint32_t)(lane & 15) * 528u
                              + (uint32_t)(wn0 + p * 16 + ((lane >> 4) * 8)) * 2u;
                ldsm_x4_t(rb, addr);
#pragma unroll
                for (int mt = 0; mt < 2; mt++) {
                    mma_bf16(acc[mt][2 * p + 0], ra[mt], rb + 0);
                    mma_bf16(acc[mt][2 * p + 1], ra[mt], rb + 2);
                }
            }
        }
        if (it < 15) {
            int nb = (it + 1) & 1;
            *(uint4*)(Bsm + nb * 16 * 264 + brow * 264 + bq * 8) = bReg0;
            *(uint4*)(Bsm + nb * 16 * 264 + (brow + 8) * 264 + bq * 8) = bReg1;
            __syncthreads();
        }
    }

    // epilogue: store bf16 Y
    const int groupID = lane >> 2;
    const int tig = lane & 3;
#pragma unroll
    for (int nt = 0; nt < 8; nt++) {
        const int col = wn0 + nt * 8 + tig * 2;
#pragma unroll
        for (int mt = 0; mt < 2; mt++) {
            const int row0 = bm0 + wm0 + mt * 16 + groupID;
            if (row0 < M) {
                __nv_bfloat162 h = __floats2bfloat162_rn(acc[mt][nt][0], acc[mt][nt][1]);
                *(__nv_bfloat162*)(Y + (size_t)row0 * 256 + col) = h;
            }
            const int row1 = row0 + 8;
            if (row1 < M) {
                __nv_bfloat162 h = __floats2bfloat162_rn(acc[mt][nt][2], acc[mt][nt][3]);
                *(__nv_bfloat162*)(Y + (size_t)row1 * 256 + col) = h;
            }
        }
    }
}

// ---------------- gather_ep: warp-per-row bf16 Y gather + epilogue ----------
#define GR_ROWS 64
#define GR_UB   ((N_USER + GR_ROWS - 1) / GR_ROWS)   // 1563
#define GR_GB   ((N_GAME + GR_ROWS - 1) / GR_ROWS)   // 782

__global__ __launch_bounds__(256)
void gather_ep(const int* __restrict__ rp_u, const int* __restrict__ srcs_u,
               const int* __restrict__ rp_g, const int* __restrict__ srcs_g,
               const __nv_bfloat16* __restrict__ Yu, const __nv_bfloat16* __restrict__ Yg,
               const float* __restrict__ x_user, const float* __restrict__ x_game,
               const float* __restrict__ eu, const float* __restrict__ eg,
               const float* __restrict__ bout_u, const float* __restrict__ bout_g,
               float* __restrict__ out)
{
    const int lane = threadIdx.x & 31;
    const int warp = threadIdx.x >> 5;

    const bool isU = (blockIdx.x < GR_UB);
    const int r0 = (isU ? blockIdx.x : blockIdx.x - GR_UB) * GR_ROWS;
    const int M = isU ? N_USER : N_GAME;
    const int* rowptr = isU ? rp_u : rp_g;
    const int* srcs   = isU ? srcs_u : srcs_g;
    const uint4* Y4   = (const uint4*)(isU ? Yu : Yg);
    const float* Xres = isU ? x_user : x_game;
    const float* extra = isU ? eu : eg;
    const float* bout  = isU ? bout_u : bout_g;
    float* Outb = isU ? out : out + (size_t)N_USER * DDIM;

    const float4 bo0 = *(const float4*)(bout + lane * 8);
    const float4 bo1 = *(const float4*)(bout + lane * 8 + 4);
    const float4 ev0 = *(const float4*)(extra + lane * 8);
    const float4 ev1 = *(const float4*)(extra + lane * 8 + 4);

    const int rend = (r0 + GR_ROWS < M) ? r0 + GR_ROWS : M;
#pragma unroll 1
    for (int r = r0 + warp; r < rend; r += 8) {
        const int beg = __ldg(rowptr + r);
        const int end = __ldg(rowptr + r + 1);
        float acc[8];
#pragma unroll
        for (int j = 0; j < 8; j++) acc[j] = 0.f;

        int e = beg;
        for (; e + 1 < end; e += 2) {
            int s0 = __ldg(srcs + e), s1 = __ldg(srcs + e + 1);
            uint4 v0 = Y4[(size_t)s0 * 32 + lane];
            uint4 v1 = Y4[(size_t)s1 * 32 + lane];
            float2 f;
            f = __bfloat1622float2(*(__nv_bfloat162*)&v0.x); acc[0] += f.x; acc[1] += f.y;
            f = __bfloat1622float2(*(__nv_bfloat162*)&v0.y); acc[2] += f.x; acc[3] += f.y;
            f = __bfloat1622float2(*(__nv_bfloat162*)&v0.z); acc[4] += f.x; acc[5] += f.y;
            f = __bfloat1622float2(*(__nv_bfloat162*)&v0.w); acc[6] += f.x; acc[7] += f.y;
            f = __bfloat1622float2(*(__nv_bfloat162*)&v1.x); acc[0] += f.x; acc[1] += f.y;
            f = __bfloat1622float2(*(__nv_bfloat162*)&v1.y); acc[2] += f.x; acc[3] += f.y;
            f = __bfloat1622float2(*(__nv_bfloat162*)&v1.z); acc[4] += f.x; acc[5] += f.y;
            f = __bfloat1622float2(*(__nv_bfloat162*)&v1.w); acc[6] += f.x; acc[7] += f.y;
        }
        if (e < end) {
            int s0 = __ldg(srcs + e);
            uint4 v0 = Y4[(size_t)s0 * 32 + lane];
            float2 f;
            f = __bfloat1622float2(*(__nv_bfloat162*)&v0.x); acc[0] += f.x; acc[1] += f.y;
            f = __bfloat1622float2(*(__nv_bfloat162*)&v0.y); acc[2] += f.x; acc[3] += f.y;
            f = __bfloat1622float2(*(__nv_bfloat162*)&v0.z); acc[4] += f.x; acc[5] += f.y;
            f = __bfloat1622float2(*(__nv_bfloat162*)&v0.w); acc[6] += f.x; acc[7] += f.y;
        }

        const int deg = end - beg;
        const float inv = 1.0f / (float)(deg > 1 ? deg : 1);
        const float on = (deg > 0) ? 1.0f : 0.0f;
        const float4 x0 = *(const float4*)(Xres + (size_t)r * 256 + lane * 8);
        const float4 x1 = *(const float4*)(Xres + (size_t)r * 256 + lane * 8 + 4);
        float4 o0, o1;
        o0.x = fmaxf(acc[0] * inv + bo0.x + on * ev0.x + x0.x, 0.f);
        o0.y = fmaxf(acc[1] * inv + bo0.y + on * ev0.y + x0.y, 0.f);
        o0.z = fmaxf(acc[2] * inv + bo0.z + on * ev0.z + x0.z, 0.f);
        o0.w = fmaxf(acc[3] * inv + bo0.w + on * ev0.w + x0.w, 0.f);
        o1.x = fmaxf(acc[4] * inv + bo1.x + on * ev1.x + x1.x, 0.f);
        o1.y = fmaxf(acc[5] * inv + bo1.y + on * ev1.y + x1.y, 0.f);
        o1.z = fmaxf(acc[6] * inv + bo1.z + on * ev1.z + x1.z, 0.f);
        o1.w = fmaxf(acc[7] * inv + bo1.w + on * ev1.w + x1.w, 0.f);
        *(float4*)(Outb + (size_t)r * 256 + lane * 8) = o0;
        *(float4*)(Outb + (size_t)r * 256 + lane * 8 + 4) = o1;
    }
}

// ---------------- host launch ----------------
extern "C" void kernel_launch(void* const* d_in, const int* in_sizes, int n_in,
                              void* d_out, int out_size)
{
    const float* x_user    = (const float*)d_in[0];
    const float* x_game    = (const float*)d_in[1];
    const float* Wv_user   = (const float*)d_in[6];
    const float* bv_user   = (const float*)d_in[7];
    const float* Wout_user = (const float*)d_in[8];
    const float* bout_user = (const float*)d_in[9];
    const float* Wv_game   = (const float*)d_in[14];
    const float* bv_game   = (const float*)d_in[15];
    const float* Wout_game = (const float*)d_in[16];
    const float* bout_game = (const float*)d_in[17];
    const float* Wm_played = (const float*)d_in[20];
    const float* bm_played = (const float*)d_in[21];
    const float* Wm_rev    = (const float*)d_in[24];
    const float* bm_rev    = (const float*)d_in[25];
    const int* ps = (const int*)d_in[26];
    const int* pd = (const int*)d_in[27];
    const int* rs = (const int*)d_in[28];
    const int* rd = (const int*)d_in[29];
    const int E = in_sizes[26];

    float* out = (float*)d_out;

    float *tmpA, *tmpB, *eu, *eg;
    int *rp_u, *rp_g, *cur_u, *cur_g, *srcs_u, *srcs_g, *part_u, *part_g;
    __nv_bfloat16 *Wub, *Wgb, *Yg, *Yu;
    cudaGetSymbolAddress((void**)&rp_u,   g_rp_u);
    cudaGetSymbolAddress((void**)&rp_g,   g_rp_g);
    cudaGetSymbolAddress((void**)&cur_u,  g_cur_u);
    cudaGetSymbolAddress((void**)&cur_g,  g_cur_g);
    cudaGetSymbolAddress((void**)&srcs_u, g_srcs_u);
    cudaGetSymbolAddress((void**)&srcs_g, g_srcs_g);
    cudaGetSymbolAddress((void**)&part_u, g_part_u);
    cudaGetSymbolAddress((void**)&part_g, g_part_g);
    cudaGetSymbolAddress((void**)&tmpA,   g_tmpA);
    cudaGetSymbolAddress((void**)&tmpB,   g_tmpB);
    cudaGetSymbolAddress((void**)&Wub,    g_Wub);
    cudaGetSymbolAddress((void**)&Wgb,    g_Wgb);
    cudaGetSymbolAddress((void**)&eu,     g_eu);
    cudaGetSymbolAddress((void**)&eg,     g_eg);
    cudaGetSymbolAddress((void**)&Yg,     g_Yg);
    cudaGetSymbolAddress((void**)&Yu,     g_Yu);

    cudaFuncSetAttribute(gemmY,
                         cudaFuncAttributeMaxDynamicSharedMemorySize, SMY_TOTAL);

    cudaMemsetAsync(rp_u, 0, (size_t)(N_USER + 1) * sizeof(int));
    cudaMemsetAsync(rp_g, 0, (size_t)(N_GAME + 1) * sizeof(int));

    const int len_u = N_USER + 1, len_g = N_GAME + 1;
    const int sgx = (len_u + 1023) / 1024;

    // idx 2: weight-chain GEMM pair + histogram
    k0_gemm_hist<<<dim3(4, 4, 4), 256>>>(Wm_played, Wout_game, tmpA,
                                         Wm_rev, Wout_user, tmpB,
                                         pd, rd, E, rp_g, rp_u);
    // idx 3: bf16 weight GEMM pair + bias combo
    k1_gemmbf_combo<<<dim3(4, 4, 3), 256>>>(Wv_user, tmpA, Wgb,
                                            Wv_game, tmpB, Wub, 0.125f,
                                            bv_user, tmpA, bm_played, Wout_game, eg,
                                            bv_game, tmpB, bm_rev, Wout_user, eu);
    // idx 4: scan partials
    scanA<<<dim3(sgx, 2), 1024>>>(rp_u, len_u, part_u, rp_g, len_g, part_g);
    // idx 5 (profiled): dense streaming GEMM Y = bf16(X @ Wcombined), 2 CTA/SM
    gemmY<<<Y_UB + Y_GB, 256, SMY_TOTAL>>>(x_user, x_game, Wgb, Wub, Yg, Yu);
    // idx 6: finish scan + cursor init
    scanC<<<dim3(sgx, 2), 1024>>>(rp_u, len_u, part_u, cur_u, rp_g, len_g, part_g, cur_g);
    // idx 7: bin edges into CSR
    bin_kernel<<<(E + 255) / 256, 256>>>(ps, pd, rs, rd, E, cur_g, srcs_g, cur_u, srcs_u);
    // idx 8: bf16 gather + epilogue
    gather_ep<<<GR_UB + GR_GB, 256>>>(rp_u, srcs_u, rp_g, srcs_g, Yu, Yg,
                                      x_user, x_game, eu, eg,
                                      bout_user, bout_game, out);
}

// round 14
// speedup vs baseline: 1.3279x; 1.0025x over previous
#include <cuda_runtime.h>
#include <cuda_bf16.h>
#include <cstdint>

#define N_USER 100000
#define N_GAME 50000
#define DDIM   256
#define EMAX   200000

// ---------------- scratch (device globals) ----------------
__device__ int   g_rp_u[N_USER + 1];
__device__ int   g_rp_g[N_GAME + 1];
__device__ int   g_cur_u[N_USER];
__device__ int   g_cur_g[N_GAME];
__device__ int   g_srcs_u[EMAX];
__device__ int   g_srcs_g[EMAX];
__device__ int   g_part_u[128];
__device__ int   g_part_g[128];
__device__ float g_tmpA[DDIM * DDIM];   // Wm_played @ Wout_game
__device__ float g_tmpB[DDIM * DDIM];   // Wm_rev @ Wout_user
__device__ __nv_bfloat16 g_Wub[DDIM * DDIM];  // bf16(0.125 * Wv_game @ tmpB)
__device__ __nv_bfloat16 g_Wgb[DDIM * DDIM];  // bf16(0.125 * Wv_user @ tmpA)
__device__ float g_eu[DDIM];
__device__ float g_eg[DDIM];
__device__ __nv_bfloat16 g_Yg[(size_t)N_USER * DDIM];  // x_user @ Wgb
__device__ __nv_bfloat16 g_Yu[(size_t)N_GAME * DDIM];  // x_game @ Wub

// ---------------- kernel 0: 64x64-tile weight GEMM pair + edge histogram ----
__global__ void k0_gemm_hist(const float* __restrict__ A0, const float* __restrict__ B0,
                             float* __restrict__ C0,
                             const float* __restrict__ A1, const float* __restrict__ B1,
                             float* __restrict__ C1,
                             const int* __restrict__ pd, const int* __restrict__ rd, int E,
                             int* __restrict__ rp_g, int* __restrict__ rp_u)
{
    if (blockIdx.z >= 2) {
        int base = ((blockIdx.z - 2) * 16 + blockIdx.y * 4 + blockIdx.x) * 256 + threadIdx.x;
        for (int i = base; i < E; i += 32 * 256) {
            atomicAdd(&rp_g[pd[i] + 1], 1);
            atomicAdd(&rp_u[rd[i] + 1], 1);
        }
        return;
    }
    const float* A = blockIdx.z ? A1 : A0;
    const float* B = blockIdx.z ? B1 : B0;
    float*       C = blockIdx.z ? C1 : C0;
    __shared__ float As[16][64];
    __shared__ float Bs[16][64];
    const int tid = threadIdx.x;
    const int tx = tid & 15, ty = tid >> 4;
    const int row0 = blockIdx.y * 64, col0 = blockIdx.x * 64;
    const int arow = tid >> 2, ac4 = (tid & 3) * 4;
    const int brow = tid >> 4, bc4 = (tid & 15) * 4;
    float acc[4][4];
#pragma unroll
    for (int i = 0; i < 4; i++)
#pragma unroll
        for (int j = 0; j < 4; j++) acc[i][j] = 0.f;

    for (int kk = 0; kk < 256; kk += 16) {
        float4 av = *(const float4*)(A + (size_t)(row0 + arow) * 256 + kk + ac4);
        As[ac4 + 0][arow] = av.x;
        As[ac4 + 1][arow] = av.y;
        As[ac4 + 2][arow] = av.z;
        As[ac4 + 3][arow] = av.w;
        float4 bv = *(const float4*)(B + (size_t)(kk + brow) * 256 + col0 + bc4);
        *(float4*)&Bs[brow][bc4] = bv;
        __syncthreads();
#pragma unroll
        for (int k = 0; k < 16; k++) {
            float4 a = *(const float4*)&As[k][ty * 4];
            float4 b = *(const float4*)&Bs[k][tx * 4];
            float ar[4] = {a.x, a.y, a.z, a.w};
            float br[4] = {b.x, b.y, b.z, b.w};
#pragma unroll
            for (int i = 0; i < 4; i++)
#pragma unroll
                for (int j = 0; j < 4; j++) acc[i][j] += ar[i] * br[j];
        }
        __syncthreads();
    }
#pragma unroll
    for (int i = 0; i < 4; i++) {
        float4 o = make_float4(acc[i][0], acc[i][1], acc[i][2], acc[i][3]);
        *(float4*)(C + (size_t)(row0 + ty * 4 + i) * 256 + col0 + tx * 4) = o;
    }
}

// ---------------- kernel 1: bf16 weight GEMM pair + fused bias combo ----------
__global__ void k1_gemmbf_combo(const float* __restrict__ A0, const float* __restrict__ B0,
                                __nv_bfloat16* __restrict__ C0,
                                const float* __restrict__ A1, const float* __restrict__ B1,
                                __nv_bfloat16* __restrict__ C1, float scale,
                                const float* __restrict__ bv0, const float* __restrict__ T0,
                                const float* __restrict__ bm0, const float* __restrict__ W0,
                                float* __restrict__ e0,
                                const float* __restrict__ bv1, const float* __restrict__ T1,
                                const float* __restrict__ bm1, const float* __restrict__ W1,
                                float* __restrict__ e1)
{
    if (blockIdx.z == 2) {
        if (blockIdx.y != 0 || blockIdx.x >= 2) return;
        const float* bv = blockIdx.x ? bv1 : bv0;
        const float* T  = blockIdx.x ? T1  : T0;
        const float* bm = blockIdx.x ? bm1 : bm0;
        const float* W  = blockIdx.x ? W1  : W0;
        float*       e  = blockIdx.x ? e1  : e0;
        int n = threadIdx.x;
        float acc = 0.f;
#pragma unroll 8
        for (int j = 0; j < 256; j++)
            acc += bv[j] * T[j * 256 + n] + bm[j] * W[j * 256 + n];
        e[n] = 0.125f * acc;
        return;
    }
    const float* A = blockIdx.z ? A1 : A0;
    const float* B = blockIdx.z ? B1 : B0;
    __nv_bfloat16* C = blockIdx.z ? C1 : C0;
    __shared__ float As[16][64];
    __shared__ float Bs[16][64];
    const int tid = threadIdx.x;
    const int tx = tid & 15, ty = tid >> 4;
    const int row0 = blockIdx.y * 64, col0 = blockIdx.x * 64;
    const int arow = tid >> 2, ac4 = (tid & 3) * 4;
    const int brow = tid >> 4, bc4 = (tid & 15) * 4;
    float acc[4][4];
#pragma unroll
    for (int i = 0; i < 4; i++)
#pragma unroll
        for (int j = 0; j < 4; j++) acc[i][j] = 0.f;

    for (int kk = 0; kk < 256; kk += 16) {
        float4 av = *(const float4*)(A + (size_t)(row0 + arow) * 256 + kk + ac4);
        As[ac4 + 0][arow] = av.x;
        As[ac4 + 1][arow] = av.y;
        As[ac4 + 2][arow] = av.z;
        As[ac4 + 3][arow] = av.w;
        float4 bv = *(const float4*)(B + (size_t)(kk + brow) * 256 + col0 + bc4);
        *(float4*)&Bs[brow][bc4] = bv;
        __syncthreads();
#pragma unroll
        for (int k = 0; k < 16; k++) {
            float4 a = *(const float4*)&As[k][ty * 4];
            float4 b = *(const float4*)&Bs[k][tx * 4];
            float ar[4] = {a.x, a.y, a.z, a.w};
            float br[4] = {b.x, b.y, b.z, b.w};
#pragma unroll
            for (int i = 0; i < 4; i++)
#pragma unroll
                for (int j = 0; j < 4; j++) acc[i][j] += ar[i] * br[j];
        }
        __syncthreads();
    }
#pragma unroll
    for (int i = 0; i < 4; i++) {
#pragma unroll
        for (int j = 0; j < 4; j++)
            C[(size_t)(row0 + ty * 4 + i) * 256 + col0 + tx * 4 + j] =
                __float2bfloat16(acc[i][j] * scale);
    }
}

// ---------------- scan kernels ----------------
__global__ void scanA(const int* __restrict__ in_u, int len_u, int* __restrict__ part_u,
                      const int* __restrict__ in_g, int len_g, int* __restrict__ part_g)
{
    const int* in  = blockIdx.y ? in_g  : in_u;
    const int len  = blockIdx.y ? len_g : len_u;
    int* part      = blockIdx.y ? part_g : part_u;
    int t = threadIdx.x;
    int idx = blockIdx.x * 1024 + t;
    int v = (idx < len) ? in[idx] : 0;
    int lane = t & 31, wid = t >> 5;
#pragma unroll
    for (int o = 16; o; o >>= 1) v += __shfl_down_sync(0xFFFFFFFFu, v, o);
    __shared__ int ws[32];
    if (lane == 0) ws[wid] = v;
    __syncthreads();
    if (wid == 0) {
        int s = ws[lane];
#pragma unroll
        for (int o = 16; o; o >>= 1) s += __shfl_down_sync(0xFFFFFFFFu, s, o);
        if (lane == 0) part[blockIdx.x] = s;
    }
}

__global__ void scanC(int* __restrict__ rp_u, int len_u, const int* __restrict__ part_u,
                      int* __restrict__ cur_u,
                      int* __restrict__ rp_g, int len_g, const int* __restrict__ part_g,
                      int* __restrict__ cur_g)
{
    int* rp         = blockIdx.y ? rp_g  : rp_u;
    const int len   = blockIdx.y ? len_g : len_u;
    const int* part = blockIdx.y ? part_g : part_u;
    int* cur        = blockIdx.y ? cur_g : cur_u;

    __shared__ int sp[128];
    int t = threadIdx.x;
    if (t < 128) sp[t] = (t < (int)gridDim.x) ? part[t] : 0;
    __syncthreads();
    int offset = 0;
    for (int j = 0; j < (int)blockIdx.x; j++) offset += sp[j];

    int idx = blockIdx.x * 1024 + t;
    int x = (idx < len) ? rp[idx] : 0;
    int lane = t & 31, wid = t >> 5;
#pragma unroll
    for (int o = 1; o < 32; o <<= 1) {
        int n = __shfl_up_sync(0xFFFFFFFFu, x, o);
        if (lane >= o) x += n;
    }
    __shared__ int wsum[32];
    if (lane == 31) wsum[wid] = x;
    __syncthreads();
    if (wid == 0) {
        int y = wsum[lane];
#pragma unroll
        for (int o = 1; o < 32; o <<= 1) {
            int n = __shfl_up_sync(0xFFFFFFFFu, y, o);
            if (lane >= o) y += n;
        }
        wsum[lane] = y;
    }
    __syncthreads();
    int incl = x + (wid > 0 ? wsum[wid - 1] : 0) + offset;
    if (idx < len) {
        rp[idx] = incl;
        if (idx < len - 1) cur[idx] = incl;
    }
}

__global__ void bin_kernel(const int* __restrict__ ps, const int* __restrict__ pd,
                           const int* __restrict__ rs, const int* __restrict__ rd, int E,
                           int* __restrict__ cur_g, int* __restrict__ srcs_g,
                           int* __restrict__ cur_u, int* __restrict__ srcs_u)
{
    int i = blockIdx.x * blockDim.x + threadIdx.x;
    if (i < E) {
        int dg = pd[i];
        int p = atomicAdd(&cur_g[dg], 1);
        srcs_g[p] = ps[i];
        int du = rd[i];
        int q = atomicAdd(&cur_u[du], 1);
        srcs_u[q] = rs[i];
    }
}

// ---------------- MMA helpers ----------------
__device__ __forceinline__ uint32_t smem_u32(const void* p)
{
    return (uint32_t)__cvta_generic_to_shared(p);
}

__device__ __forceinline__ void ldsm_x4(uint32_t* r, uint32_t addr)
{
    asm volatile("ldmatrix.sync.aligned.m8n8.x4.shared.b16 {%0,%1,%2,%3}, [%4];"
                 : "=r"(r[0]), "=r"(r[1]), "=r"(r[2]), "=r"(r[3]) : "r"(addr));
}

__device__ __forceinline__ void ldsm_x4_t(uint32_t* r, uint32_t addr)
{
    asm volatile("ldmatrix.sync.aligned.m8n8.x4.trans.shared.b16 {%0,%1,%2,%3}, [%4];"
                 : "=r"(r[0]), "=r"(r[1]), "=r"(r[2]), "=r"(r[3]) : "r"(addr));
}

__device__ __forceinline__ void mma_bf16(float* c, const uint32_t* a, const uint32_t* b)
{
    asm volatile("mma.sync.aligned.m16n8k16.row.col.f32.bf16.bf16.f32 "
                 "{%0,%1,%2,%3}, {%4,%5,%6,%7}, {%8,%9}, {%0,%1,%2,%3};"
                 : "+f"(c[0]), "+f"(c[1]), "+f"(c[2]), "+f"(c[3])
                 : "r"(a[0]), "r"(a[1]), "r"(a[2]), "r"(a[3]), "r"(b[0]), "r"(b[1]));
}

// ---------------- gemmY v3: persistent blocks, B fully smem-resident ----------
// 148 blocks (99 user / 49 game), 256 threads, warp grid 2M x 4N, warp tile 32x64.
// smem: B 256x264 bf16 (135168) + A 2 x 64x264 bf16 (67584) = 202752 B -> 1 CTA/SM.
#define NT_U   ((N_USER + 63) / 64)   // 1563
#define NT_G   ((N_GAME + 63) / 64)   // 782
#define BLK_U  99
#define BLK_G  49
#define SMP_A_OFF   (256 * 264 * 2)               // 135168
#define SMP_TOTAL   (SMP_A_OFF + 2 * 64 * 264 * 2)  // 202752

__global__ __launch_bounds__(256, 1)
void gemmY(const float* __restrict__ x_user, const float* __restrict__ x_game,
           const __nv_bfloat16* __restrict__ Wgb, const __nv_bfloat16* __restrict__ Wub,
           __nv_bfloat16* __restrict__ Yg, __nv_bfloat16* __restrict__ Yu)
{
    extern __shared__ char smem[];
    __nv_bfloat16* Bsm = (__nv_bfloat16*)smem;
    __nv_bfloat16* Abf = (__nv_bfloat16*)(smem + SMP_A_OFF);

    const int tid = threadIdx.x;
    const int lane = tid & 31;
    const int warp = tid >> 5;

    const bool isU = (blockIdx.x < BLK_U);
    const int b = isU ? blockIdx.x : blockIdx.x - BLK_U;
    const int stride = isU ? BLK_U : BLK_G;
    const int ntile = isU ? NT_U : NT_G;
    const int M = isU ? N_USER : N_GAME;
    const float* X = isU ? x_user : x_game;
    const __nv_bfloat16* Wb = isU ? Wgb : Wub;
    __nv_bfloat16* Y = isU ? Yg : Yu;

    // ---- load full B into smem once (256 rows x 256 bf16) ----
    {
        const int brow = tid >> 5;      // 0..7
        const int bq = tid & 31;        // 0..31
#pragma unroll
        for (int c = 0; c < 16; c++) {
            int r0 = c * 16 + brow;
            int r1 = r0 + 8;
            uint4 v0 = *(const uint4*)(Wb + (size_t)r0 * 256 + bq * 8);
            uint4 v1 = *(const uint4*)(Wb + (size_t)r1 * 256 + bq * 8);
            *(uint4*)(Bsm + r0 * 264 + bq * 8) = v0;
            *(uint4*)(Bsm + r1 * 264 + bq * 8) = v1;
        }
    }

    // ---- A tile loader (warp-per-row, 8 rows/warp) ----
    const float4* X4 = (const float4*)X;
    auto loadA = [&](int bm0, int buf) {
#pragma unroll
        for (int i = 0; i < 8; i++) {
            const int rl = warp * 8 + i;
            const int r = bm0 + rl;
            float4 a0 = make_float4(0.f, 0.f, 0.f, 0.f);
            float4 a1 = make_float4(0.f, 0.f, 0.f, 0.f);
            if (r < M) {
                a0 = X4[(size_t)r * 64 + lane];
                a1 = X4[(size_t)r * 64 + 32 + lane];
            }
            __nv_bfloat162 h00 = __floats2bfloat162_rn(a0.x, a0.y);
            __nv_bfloat162 h01 = __floats2bfloat162_rn(a0.z, a0.w);
            __nv_bfloat162 h10 = __floats2bfloat162_rn(a1.x, a1.y);
            __nv_bfloat162 h11 = __floats2bfloat162_rn(a1.z, a1.w);
            uint2 w0; w0.x = *(uint32_t*)&h00; w0.y = *(uint32_t*)&h01;
            uint2 w1; w1.x = *(uint32_t*)&h10; w1.y = *(uint32_t*)&h11;
            __nv_bfloat16* dst = Abf + buf * (64 * 264) + rl * 264;
            *(uint2*)(dst + lane * 4) = w0;
            *(uint2*)(dst + 128 + lane * 4) = w1;
        }
    };

    if (b < ntile) loadA(b * 64, 0);
    __syncthreads();

    const int wm0 = (warp >> 2) * 32;   // 0,32
    const int wn0 = (warp & 3) * 64;    // 0,64,128,192
    const uint32_t bBase = smem_u32(Bsm);
    const uint32_t aBase = smem_u32(Abf);
    const int groupID = lane >> 2;
    const int tig = lane & 3;

    int bufi = 0;
    for (int t = b; t < ntile; t += stride, bufi ^= 1) {
        const int bm0 = t * 64;

        float acc[2][8][4];
#pragma unroll
        for (int mt = 0; mt < 2; mt++)
#pragma unroll
            for (int nt = 0; nt < 8; nt++)
#pragma unroll
                for (int j = 0; j < 4; j++) acc[mt][nt][j] = 0.f;

        const uint32_t aB = aBase + (uint32_t)bufi * (64 * 264 * 2);
        // mainloop: no syncs, B+A resident
#pragma unroll 4
        for (int it = 0; it < 16; it++) {
            uint32_t ra[2][4];
#pragma unroll
            for (int mt = 0; mt < 2; mt++) {
                uint32_t addr = aB + (uint32_t)(wm0 + mt * 16 + (lane & 15)) * 528u
                              + (uint32_t)(lane >> 4) * 16u + (uint32_t)it * 32u;
                ldsm_x4(ra[mt], addr);
            }
#pragma unroll
            for (int p = 0; p < 4; p++) {
                uint32_t rb[4];
                uint32_t addr = bBase + (uint32_t)(it * 16 + (lane & 15)) * 528u
                              + (uint32_t)(wn0 + p * 16 + ((lane >> 4) * 8)) * 2u;
                ldsm_x4_t(rb, addr);
#pragma unroll
                for (int mt = 0; mt < 2; mt++) {
                    mma_bf16(acc[mt][2 * p + 0], ra[mt], rb + 0);
                    mma_bf16(acc[mt][2 * p + 1], ra[mt], rb + 2);
                }
            }
        }

        // prefetch next A tile into the other buffer (safe: not read this tile)
        const int tn = t + stride;
        if (tn < ntile) loadA(tn * 64, bufi ^ 1);

        // store Y tile
#pragma unroll
        for (int nt = 0; nt < 8; nt++) {
            const int col = wn0 + nt * 8 + tig * 2;
#pragma unroll
            for (int mt = 0; mt < 2; mt++) {
                const int row0 = bm0 + wm0 + mt * 16 + groupID;
                if (row0 < M) {
                    __nv_bfloat162 h = __floats2bfloat162_rn(acc[mt][nt][0], acc[mt][nt][1]);
                    *(__nv_bfloat162*)(Y + (size_t)row0 * 256 + col) = h;
                }
                const int row1 = row0 + 8;
                if (row1 < M) {
                    __nv_bfloat162 h = __floats2bfloat162_rn(acc[mt][nt][2], acc[mt][nt][3]);
                    *(__nv_bfloat162*)(Y + (size_t)row1 * 256 + col) = h;
                }
            }
        }
        __syncthreads();
    }
}

// ---------------- gather_ep: warp-per-row bf16 Y gather + epilogue ----------
#define GR_ROWS 64
#define GR_UB   ((N_USER + GR_ROWS - 1) / GR_ROWS)   // 1563
#define GR_GB   ((N_GAME + GR_ROWS - 1) / GR_ROWS)   // 782

__global__ __launch_bounds__(256)
void gather_ep(const int* __restrict__ rp_u, const int* __restrict__ srcs_u,
               const int* __restrict__ rp_g, const int* __restrict__ srcs_g,
               const __nv_bfloat16* __restrict__ Yu, const __nv_bfloat16* __restrict__ Yg,
               const float* __restrict__ x_user, const float* __restrict__ x_game,
               const float* __restrict__ eu, const float* __restrict__ eg,
               const float* __restrict__ bout_u, const float* __restrict__ bout_g,
               float* __restrict__ out)
{
    const int lane = threadIdx.x & 31;
    const int warp = threadIdx.x >> 5;

    const bool isU = (blockIdx.x < GR_UB);
    const int r0 = (isU ? blockIdx.x : blockIdx.x - GR_UB) * GR_ROWS;
    const int M = isU ? N_USER : N_GAME;
    const int* rowptr = isU ? rp_u : rp_g;
    const int* srcs   = isU ? srcs_u : srcs_g;
    const uint4* Y4   = (const uint4*)(isU ? Yu : Yg);
    const float* Xres = isU ? x_user : x_game;
    const float* extra = isU ? eu : eg;
    const float* bout  = isU ? bout_u : bout_g;
    float* Outb = isU ? out : out + (size_t)N_USER * DDIM;

    const float4 bo0 = *(const float4*)(bout + lane * 8);
    const float4 bo1 = *(const float4*)(bout + lane * 8 + 4);
    const float4 ev0 = *(const float4*)(extra + lane * 8);
    const float4 ev1 = *(const float4*)(extra + lane * 8 + 4);

    const int rend = (r0 + GR_ROWS < M) ? r0 + GR_ROWS : M;
#pragma unroll 1
    for (int r = r0 + warp; r < rend; r += 8) {
        const int beg = __ldg(rowptr + r);
        const int end = __ldg(rowptr + r + 1);
        float acc[8];
#pragma unroll
        for (int j = 0; j < 8; j++) acc[j] = 0.f;

        int e = beg;
        for (; e + 1 < end; e += 2) {
            int s0 = __ldg(srcs + e), s1 = __ldg(srcs + e + 1);
            uint4 v0 = Y4[(size_t)s0 * 32 + lane];
            uint4 v1 = Y4[(size_t)s1 * 32 + lane];
            float2 f;
            f = __bfloat1622float2(*(__nv_bfloat162*)&v0.x); acc[0] += f.x; acc[1] += f.y;
            f = __bfloat1622float2(*(__nv_bfloat162*)&v0.y); acc[2] += f.x; acc[3] += f.y;
            f = __bfloat1622float2(*(__nv_bfloat162*)&v0.z); acc[4] += f.x; acc[5] += f.y;
            f = __bfloat1622float2(*(__nv_bfloat162*)&v0.w); acc[6] += f.x; acc[7] += f.y;
            f = __bfloat1622float2(*(__nv_bfloat162*)&v1.x); acc[0] += f.x; acc[1] += f.y;
            f = __bfloat1622float2(*(__nv_bfloat162*)&v1.y); acc[2] += f.x; acc[3] += f.y;
            f = __bfloat1622float2(*(__nv_bfloat162*)&v1.z); acc[4] += f.x; acc[5] += f.y;
            f = __bfloat1622float2(*(__nv_bfloat162*)&v1.w); acc[6] += f.x; acc[7] += f.y;
        }
        if (e < end) {
            int s0 = __ldg(srcs + e);
            uint4 v0 = Y4[(size_t)s0 * 32 + lane];
            float2 f;
            f = __bfloat1622float2(*(__nv_bfloat162*)&v0.x); acc[0] += f.x; acc[1] += f.y;
            f = __bfloat1622float2(*(__nv_bfloat162*)&v0.y); acc[2] += f.x; acc[3] += f.y;
            f = __bfloat1622float2(*(__nv_bfloat162*)&v0.z); acc[4] += f.x; acc[5] += f.y;
            f = __bfloat1622float2(*(__nv_bfloat162*)&v0.w); acc[6] += f.x; acc[7] += f.y;
        }

        const int deg = end - beg;
        const float inv = 1.0f / (float)(deg > 1 ? deg : 1);
        const float on = (deg > 0) ? 1.0f : 0.0f;
        const float4 x0 = *(const float4*)(Xres + (size_t)r * 256 + lane * 8);
        const float4 x1 = *(const float4*)(Xres + (size_t)r * 256 + lane * 8 + 4);
        float4 o0, o1;
        o0.x = fmaxf(acc[0] * inv + bo0.x + on * ev0.x + x0.x, 0.f);
        o0.y = fmaxf(acc[1] * inv + bo0.y + on * ev0.y + x0.y, 0.f);
        o0.z = fmaxf(acc[2] * inv + bo0.z + on * ev0.z + x0.z, 0.f);
        o0.w = fmaxf(acc[3] * inv + bo0.w + on * ev0.w + x0.w, 0.f);
        o1.x = fmaxf(acc[4] * inv + bo1.x + on * ev1.x + x1.x, 0.f);
        o1.y = fmaxf(acc[5] * inv + bo1.y + on * ev1.y + x1.y, 0.f);
        o1.z = fmaxf(acc[6] * inv + bo1.z + on * ev1.z + x1.z, 0.f);
        o1.w = fmaxf(acc[7] * inv + bo1.w + on * ev1.w + x1.w, 0.f);
        *(float4*)(Outb + (size_t)r * 256 + lane * 8) = o0;
        *(float4*)(Outb + (size_t)r * 256 + lane * 8 + 4) = o1;
    }
}

// ---------------- host launch ----------------
extern "C" void kernel_launch(void* const* d_in, const int* in_sizes, int n_in,
                              void* d_out, int out_size)
{
    const float* x_user    = (const float*)d_in[0];
    const float* x_game    = (const float*)d_in[1];
    const float* Wv_user   = (const float*)d_in[6];
    const float* bv_user   = (const float*)d_in[7];
    const float* Wout_user = (const float*)d_in[8];
    const float* bout_user = (const float*)d_in[9];
    const float* Wv_game   = (const float*)d_in[14];
    const float* bv_game   = (const float*)d_in[15];
    const float* Wout_game = (const float*)d_in[16];
    const float* bout_game = (const float*)d_in[17];
    const float* Wm_played = (const float*)d_in[20];
    const float* bm_played = (const float*)d_in[21];
    const float* Wm_rev    = (const float*)d_in[24];
    const float* bm_rev    = (const float*)d_in[25];
    const int* ps = (const int*)d_in[26];
    const int* pd = (const int*)d_in[27];
    const int* rs = (const int*)d_in[28];
    const int* rd = (const int*)d_in[29];
    const int E = in_sizes[26];

    float* out = (float*)d_out;

    float *tmpA, *tmpB, *eu, *eg;
    int *rp_u, *rp_g, *cur_u, *cur_g, *srcs_u, *srcs_g, *part_u, *part_g;
    __nv_bfloat16 *Wub, *Wgb, *Yg, *Yu;
    cudaGetSymbolAddress((void**)&rp_u,   g_rp_u);
    cudaGetSymbolAddress((void**)&rp_g,   g_rp_g);
    cudaGetSymbolAddress((void**)&cur_u,  g_cur_u);
    cudaGetSymbolAddress((void**)&cur_g,  g_cur_g);
    cudaGetSymbolAddress((void**)&srcs_u, g_srcs_u);
    cudaGetSymbolAddress((void**)&srcs_g, g_srcs_g);
    cudaGetSymbolAddress((void**)&part_u, g_part_u);
    cudaGetSymbolAddress((void**)&part_g, g_part_g);
    cudaGetSymbolAddress((void**)&tmpA,   g_tmpA);
    cudaGetSymbolAddress((void**)&tmpB,   g_tmpB);
    cudaGetSymbolAddress((void**)&Wub,    g_Wub);
    cudaGetSymbolAddress((void**)&Wgb,    g_Wgb);
    cudaGetSymbolAddress((void**)&eu,     g_eu);
    cudaGetSymbolAddress((void**)&eg,     g_eg);
    cudaGetSymbolAddress((void**)&Yg,     g_Yg);
    cudaGetSymbolAddress((void**)&Yu,     g_Yu);

    cudaFuncSetAttribute(gemmY,
                         cudaFuncAttributeMaxDynamicSharedMemorySize, SMP_TOTAL);

    cudaMemsetAsync(rp_u, 0, (size_t)(N_USER + 1) * sizeof(int));
    cudaMemsetAsync(rp_g, 0, (size_t)(N_GAME + 1) * sizeof(int));

    const int len_u = N_USER + 1, len_g = N_GAME + 1;
    const int sgx = (len_u + 1023) / 1024;

    // idx 2: weight-chain GEMM pair + histogram
    k0_gemm_hist<<<dim3(4, 4, 4), 256>>>(Wm_played, Wout_game, tmpA,
                                         Wm_rev, Wout_user, tmpB,
                                         pd, rd, E, rp_g, rp_u);
    // idx 3: bf16 weight GEMM pair + bias combo
    k1_gemmbf_combo<<<dim3(4, 4, 3), 256>>>(Wv_user, tmpA, Wgb,
                                            Wv_game, tmpB, Wub, 0.125f,
                                            bv_user, tmpA, bm_played, Wout_game, eg,
                                            bv_game, tmpB, bm_rev, Wout_user, eu);
    // idx 4: scan partials
    scanA<<<dim3(sgx, 2), 1024>>>(rp_u, len_u, part_u, rp_g, len_g, part_g);
    // idx 5 (profiled): persistent GEMM Y = bf16(X @ Wcombined), B smem-resident
    gemmY<<<BLK_U + BLK_G, 256, SMP_TOTAL>>>(x_user, x_game, Wgb, Wub, Yg, Yu);
    // idx 6: finish scan + cursor init
    scanC<<<dim3(sgx, 2), 1024>>>(rp_u, len_u, part_u, cur_u, rp_g, len_g, part_g, cur_g);
    // idx 7: bin edges into CSR
    bin_kernel<<<(E + 255) / 256, 256>>>(ps, pd, rs, rd, E, cur_g, srcs_g, cur_u, srcs_u);
    // idx 8: bf16 gather + epilogue
    gather_ep<<<GR_UB + GR_GB, 256>>>(rp_u, srcs_u, rp_g, srcs_g, Yu, Yg,
                                      x_user, x_game, eu, eg,
                                      bout_user, bout_game, out);
}

// round 16
// speedup vs baseline: 1.3712x; 1.0326x over previous
#include <cuda_runtime.h>
#include <cuda_bf16.h>
#include <cstdint>

#define N_USER 100000
#define N_GAME 50000
#define DDIM   256
#define EMAX   200000

// ---------------- scratch (device globals) ----------------
__device__ int   g_rp_u[N_USER + 1];
__device__ int   g_rp_g[N_GAME + 1];
__device__ int   g_cur_u[N_USER];
__device__ int   g_cur_g[N_GAME];
__device__ int   g_srcs_u[EMAX];
__device__ int   g_srcs_g[EMAX];
__device__ int   g_part_u[128];
__device__ int   g_part_g[128];
__device__ float g_tmpA[DDIM * DDIM];   // Wm_played @ Wout_game
__device__ float g_tmpB[DDIM * DDIM];   // Wm_rev @ Wout_user
__device__ __nv_bfloat16 g_Wub[DDIM * DDIM];  // bf16(0.125 * Wv_game @ tmpB)
__device__ __nv_bfloat16 g_Wgb[DDIM * DDIM];  // bf16(0.125 * Wv_user @ tmpA)
__device__ float g_eu[DDIM];
__device__ float g_eg[DDIM];
__device__ __nv_bfloat16 g_Yg[(size_t)N_USER * DDIM];  // x_user @ Wgb
__device__ __nv_bfloat16 g_Yu[(size_t)N_GAME * DDIM];  // x_game @ Wub

// ---------------- side stream for CSR-chain overlap (created pre-main) ------
static cudaStream_t g_s2 = 0;
static cudaEvent_t  g_e1 = 0, g_e2 = 0;
namespace {
struct StreamInit {
    StreamInit() {
        if (cudaStreamCreateWithFlags(&g_s2, cudaStreamNonBlocking) != cudaSuccess)
            g_s2 = 0;
        if (cudaEventCreateWithFlags(&g_e1, cudaEventDisableTiming) != cudaSuccess)
            g_e1 = 0;
        if (cudaEventCreateWithFlags(&g_e2, cudaEventDisableTiming) != cudaSuccess)
            g_e2 = 0;
        if (!g_e1 || !g_e2) g_s2 = 0;   // fall back to fully serial legacy stream
    }
};
StreamInit g_stream_init;
}

// ---------------- kernel 0: 64x64-tile weight GEMM pair + edge histogram ----
__global__ void k0_gemm_hist(const float* __restrict__ A0, const float* __restrict__ B0,
                             float* __restrict__ C0,
                             const float* __restrict__ A1, const float* __restrict__ B1,
                             float* __restrict__ C1,
                             const int* __restrict__ pd, const int* __restrict__ rd, int E,
                             int* __restrict__ rp_g, int* __restrict__ rp_u)
{
    if (blockIdx.z >= 2) {
        int base = ((blockIdx.z - 2) * 16 + blockIdx.y * 4 + blockIdx.x) * 256 + threadIdx.x;
        for (int i = base; i < E; i += 32 * 256) {
            atomicAdd(&rp_g[pd[i] + 1], 1);
            atomicAdd(&rp_u[rd[i] + 1], 1);
        }
        return;
    }
    const float* A = blockIdx.z ? A1 : A0;
    const float* B = blockIdx.z ? B1 : B0;
    float*       C = blockIdx.z ? C1 : C0;
    __shared__ float As[16][64];
    __shared__ float Bs[16][64];
    const int tid = threadIdx.x;
    const int tx = tid & 15, ty = tid >> 4;
    const int row0 = blockIdx.y * 64, col0 = blockIdx.x * 64;
    const int arow = tid >> 2, ac4 = (tid & 3) * 4;
    const int brow = tid >> 4, bc4 = (tid & 15) * 4;
    float acc[4][4];
#pragma unroll
    for (int i = 0; i < 4; i++)
#pragma unroll
        for (int j = 0; j < 4; j++) acc[i][j] = 0.f;

    for (int kk = 0; kk < 256; kk += 16) {
        float4 av = *(const float4*)(A + (size_t)(row0 + arow) * 256 + kk + ac4);
        As[ac4 + 0][arow] = av.x;
        As[ac4 + 1][arow] = av.y;
        As[ac4 + 2][arow] = av.z;
        As[ac4 + 3][arow] = av.w;
        float4 bv = *(const float4*)(B + (size_t)(kk + brow) * 256 + col0 + bc4);
        *(float4*)&Bs[brow][bc4] = bv;
        __syncthreads();
#pragma unroll
        for (int k = 0; k < 16; k++) {
            float4 a = *(const float4*)&As[k][ty * 4];
            float4 b = *(const float4*)&Bs[k][tx * 4];
            float ar[4] = {a.x, a.y, a.z, a.w};
            float br[4] = {b.x, b.y, b.z, b.w};
#pragma unroll
            for (int i = 0; i < 4; i++)
#pragma unroll
                for (int j = 0; j < 4; j++) acc[i][j] += ar[i] * br[j];
        }
        __syncthreads();
    }
#pragma unroll
    for (int i = 0; i < 4; i++) {
        float4 o = make_float4(acc[i][0], acc[i][1], acc[i][2], acc[i][3]);
        *(float4*)(C + (size_t)(row0 + ty * 4 + i) * 256 + col0 + tx * 4) = o;
    }
}

// ---------------- kernel 1: bf16 weight GEMM pair + fused bias combo ----------
__global__ void k1_gemmbf_combo(const float* __restrict__ A0, const float* __restrict__ B0,
                                __nv_bfloat16* __restrict__ C0,
                                const float* __restrict__ A1, const float* __restrict__ B1,
                                __nv_bfloat16* __restrict__ C1, float scale,
                                const float* __restrict__ bv0, const float* __restrict__ T0,
                                const float* __restrict__ bm0, const float* __restrict__ W0,
                                float* __restrict__ e0,
                                const float* __restrict__ bv1, const float* __restrict__ T1,
                                const float* __restrict__ bm1, const float* __restrict__ W1,
                                float* __restrict__ e1)
{
    if (blockIdx.z == 2) {
        if (blockIdx.y != 0 || blockIdx.x >= 2) return;
        const float* bv = blockIdx.x ? bv1 : bv0;
        const float* T  = blockIdx.x ? T1  : T0;
        const float* bm = blockIdx.x ? bm1 : bm0;
        const float* W  = blockIdx.x ? W1  : W0;
        float*       e  = blockIdx.x ? e1  : e0;
        int n = threadIdx.x;
        float acc = 0.f;
#pragma unroll 8
        for (int j = 0; j < 256; j++)
            acc += bv[j] * T[j * 256 + n] + bm[j] * W[j * 256 + n];
        e[n] = 0.125f * acc;
        return;
    }
    const float* A = blockIdx.z ? A1 : A0;
    const float* B = blockIdx.z ? B1 : B0;
    __nv_bfloat16* C = blockIdx.z ? C1 : C0;
    __shared__ float As[16][64];
    __shared__ float Bs[16][64];
    const int tid = threadIdx.x;
    const int tx = tid & 15, ty = tid >> 4;
    const int row0 = blockIdx.y * 64, col0 = blockIdx.x * 64;
    const int arow = tid >> 2, ac4 = (tid & 3) * 4;
    const int brow = tid >> 4, bc4 = (tid & 15) * 4;
    float acc[4][4];
#pragma unroll
    for (int i = 0; i < 4; i++)
#pragma unroll
        for (int j = 0; j < 4; j++) acc[i][j] = 0.f;

    for (int kk = 0; kk < 256; kk += 16) {
        float4 av = *(const float4*)(A + (size_t)(row0 + arow) * 256 + kk + ac4);
        As[ac4 + 0][arow] = av.x;
        As[ac4 + 1][arow] = av.y;
        As[ac4 + 2][arow] = av.z;
        As[ac4 + 3][arow] = av.w;
        float4 bv = *(const float4*)(B + (size_t)(kk + brow) * 256 + col0 + bc4);
        *(float4*)&Bs[brow][bc4] = bv;
        __syncthreads();
#pragma unroll
        for (int k = 0; k < 16; k++) {
            float4 a = *(const float4*)&As[k][ty * 4];
            float4 b = *(const float4*)&Bs[k][tx * 4];
            float ar[4] = {a.x, a.y, a.z, a.w};
            float br[4] = {b.x, b.y, b.z, b.w};
#pragma unroll
            for (int i = 0; i < 4; i++)
#pragma unroll
                for (int j = 0; j < 4; j++) acc[i][j] += ar[i] * br[j];
        }
        __syncthreads();
    }
#pragma unroll
    for (int i = 0; i < 4; i++) {
#pragma unroll
        for (int j = 0; j < 4; j++)
            C[(size_t)(row0 + ty * 4 + i) * 256 + col0 + tx * 4 + j] =
                __float2bfloat16(acc[i][j] * scale);
    }
}

// ---------------- scan kernels ----------------
__global__ void scanA(const int* __restrict__ in_u, int len_u, int* __restrict__ part_u,
                      const int* __restrict__ in_g, int len_g, int* __restrict__ part_g)
{
    const int* in  = blockIdx.y ? in_g  : in_u;
    const int len  = blockIdx.y ? len_g : len_u;
    int* part      = blockIdx.y ? part_g : part_u;
    int t = threadIdx.x;
    int idx = blockIdx.x * 1024 + t;
    int v = (idx < len) ? in[idx] : 0;
    int lane = t & 31, wid = t >> 5;
#pragma unroll
    for (int o = 16; o; o >>= 1) v += __shfl_down_sync(0xFFFFFFFFu, v, o);
    __shared__ int ws[32];
    if (lane == 0) ws[wid] = v;
    __syncthreads();
    if (wid == 0) {
        int s = ws[lane];
#pragma unroll
        for (int o = 16; o; o >>= 1) s += __shfl_down_sync(0xFFFFFFFFu, s, o);
        if (lane == 0) part[blockIdx.x] = s;
    }
}

__global__ void scanC(int* __restrict__ rp_u, int len_u, const int* __restrict__ part_u,
                      int* __restrict__ cur_u,
                      int* __restrict__ rp_g, int len_g, const int* __restrict__ part_g,
                      int* __restrict__ cur_g)
{
    int* rp         = blockIdx.y ? rp_g  : rp_u;
    const int len   = blockIdx.y ? len_g : len_u;
    const int* part = blockIdx.y ? part_g : part_u;
    int* cur        = blockIdx.y ? cur_g : cur_u;

    __shared__ int sp[128];
    int t = threadIdx.x;
    if (t < 128) sp[t] = (t < (int)gridDim.x) ? part[t] : 0;
    __syncthreads();
    int offset = 0;
    for (int j = 0; j < (int)blockIdx.x; j++) offset += sp[j];

    int idx = blockIdx.x * 1024 + t;
    int x = (idx < len) ? rp[idx] : 0;
    int lane = t & 31, wid = t >> 5;
#pragma unroll
    for (int o = 1; o < 32; o <<= 1) {
        int n = __shfl_up_sync(0xFFFFFFFFu, x, o);
        if (lane >= o) x += n;
    }
    __shared__ int wsum[32];
    if (lane == 31) wsum[wid] = x;
    __syncthreads();
    if (wid == 0) {
        int y = wsum[lane];
#pragma unroll
        for (int o = 1; o < 32; o <<= 1) {
            int n = __shfl_up_sync(0xFFFFFFFFu, y, o);
            if (lane >= o) y += n;
        }
        wsum[lane] = y;
    }
    __syncthreads();
    int incl = x + (wid > 0 ? wsum[wid - 1] : 0) + offset;
    if (idx < len) {
        rp[idx] = incl;
        if (idx < len - 1) cur[idx] = incl;
    }
}

__global__ void bin_kernel(const int* __restrict__ ps, const int* __restrict__ pd,
                           const int* __restrict__ rs, const int* __restrict__ rd, int E,
                           int* __restrict__ cur_g, int* __restrict__ srcs_g,
                           int* __restrict__ cur_u, int* __restrict__ srcs_u)
{
    int i = blockIdx.x * blockDim.x + threadIdx.x;
    if (i < E) {
        int dg = pd[i];
        int p = atomicAdd(&cur_g[dg], 1);
        srcs_g[p] = ps[i];
        int du = rd[i];
        int q = atomicAdd(&cur_u[du], 1);
        srcs_u[q] = rs[i];
    }
}

// ---------------- MMA helpers ----------------
__device__ __forceinline__ uint32_t smem_u32(const void* p)
{
    return (uint32_t)__cvta_generic_to_shared(p);
}

__device__ __forceinline__ void ldsm_x4(uint32_t* r, uint32_t addr)
{
    asm volatile("ldmatrix.sync.aligned.m8n8.x4.shared.b16 {%0,%1,%2,%3}, [%4];"
                 : "=r"(r[0]), "=r"(r[1]), "=r"(r[2]), "=r"(r[3]) : "r"(addr));
}

__device__ __forceinline__ void ldsm_x4_t(uint32_t* r, uint32_t addr)
{
    asm volatile("ldmatrix.sync.aligned.m8n8.x4.trans.shared.b16 {%0,%1,%2,%3}, [%4];"
                 : "=r"(r[0]), "=r"(r[1]), "=r"(r[2]), "=r"(r[3]) : "r"(addr));
}

__device__ __forceinline__ void mma_bf16(float* c, const uint32_t* a, const uint32_t* b)
{
    asm volatile("mma.sync.aligned.m16n8k16.row.col.f32.bf16.bf16.f32 "
                 "{%0,%1,%2,%3}, {%4,%5,%6,%7}, {%8,%9}, {%0,%1,%2,%3};"
                 : "+f"(c[0]), "+f"(c[1]), "+f"(c[2]), "+f"(c[3])
                 : "r"(a[0]), "r"(a[1]), "r"(a[2]), "r"(a[3]), "r"(b[0]), "r"(b[1]));
}

// ---------------- gemmY: persistent blocks, B fully smem-resident (R14) ------
// 148 blocks (99 user / 49 game), 256 threads, warp grid 2M x 4N, warp tile 32x64.
// smem: B 256x264 bf16 (135168) + A 2 x 64x264 bf16 (67584) = 202752 B -> 1 CTA/SM.
#define NT_U   ((N_USER + 63) / 64)   // 1563
#define NT_G   ((N_GAME + 63) / 64)   // 782
#define BLK_U  99
#define BLK_G  49
#define SMP_A_OFF   (256 * 264 * 2)                 // 135168
#define SMP_TOTAL   (SMP_A_OFF + 2 * 64 * 264 * 2)  // 202752

__global__ __launch_bounds__(256, 1)
void gemmY(const float* __restrict__ x_user, const float* __restrict__ x_game,
           const __nv_bfloat16* __restrict__ Wgb, const __nv_bfloat16* __restrict__ Wub,
           __nv_bfloat16* __restrict__ Yg, __nv_bfloat16* __restrict__ Yu)
{
    extern __shared__ char smem[];
    __nv_bfloat16* Bsm = (__nv_bfloat16*)smem;
    __nv_bfloat16* Abf = (__nv_bfloat16*)(smem + SMP_A_OFF);

    const int tid = threadIdx.x;
    const int lane = tid & 31;
    const int warp = tid >> 5;

    const bool isU = (blockIdx.x < BLK_U);
    const int b = isU ? blockIdx.x : blockIdx.x - BLK_U;
    const int stride = isU ? BLK_U : BLK_G;
    const int ntile = isU ? NT_U : NT_G;
    const int M = isU ? N_USER : N_GAME;
    const float* X = isU ? x_user : x_game;
    const __nv_bfloat16* Wb = isU ? Wgb : Wub;
    __nv_bfloat16* Y = isU ? Yg : Yu;

    // ---- load full B into smem once (256 rows x 256 bf16) ----
    {
        const int brow = tid >> 5;
        const int bq = tid & 31;
#pragma unroll
        for (int c = 0; c < 16; c++) {
            int r0 = c * 16 + brow;
            int r1 = r0 + 8;
            uint4 v0 = *(const uint4*)(Wb + (size_t)r0 * 256 + bq * 8);
            uint4 v1 = *(const uint4*)(Wb + (size_t)r1 * 256 + bq * 8);
            *(uint4*)(Bsm + r0 * 264 + bq * 8) = v0;
            *(uint4*)(Bsm + r1 * 264 + bq * 8) = v1;
        }
    }

    // ---- A tile loader (warp-per-row, 8 rows/warp) ----
    const float4* X4 = (const float4*)X;
    auto loadA = [&](int bm0, int buf) {
#pragma unroll
        for (int i = 0; i < 8; i++) {
            const int rl = warp * 8 + i;
            const int r = bm0 + rl;
            float4 a0 = make_float4(0.f, 0.f, 0.f, 0.f);
            float4 a1 = make_float4(0.f, 0.f, 0.f, 0.f);
            if (r < M) {
                a0 = X4[(size_t)r * 64 + lane];
                a1 = X4[(size_t)r * 64 + 32 + lane];
            }
            __nv_bfloat162 h00 = __floats2bfloat162_rn(a0.x, a0.y);
            __nv_bfloat162 h01 = __floats2bfloat162_rn(a0.z, a0.w);
            __nv_bfloat162 h10 = __floats2bfloat162_rn(a1.x, a1.y);
            __nv_bfloat162 h11 = __floats2bfloat162_rn(a1.z, a1.w);
            uint2 w0; w0.x = *(uint32_t*)&h00; w0.y = *(uint32_t*)&h01;
            uint2 w1; w1.x = *(uint32_t*)&h10; w1.y = *(uint32_t*)&h11;
            __nv_bfloat16* dst = Abf + buf * (64 * 264) + rl * 264;
            *(uint2*)(dst + lane * 4) = w0;
            *(uint2*)(dst + 128 + lane * 4) = w1;
        }
    };

    if (b < ntile) loadA(b * 64, 0);
    __syncthreads();

    const int wm0 = (warp >> 2) * 32;
    const int wn0 = (warp & 3) * 64;
    const uint32_t bBase = smem_u32(Bsm);
    const uint32_t aBase = smem_u32(Abf);
    const int groupID = lane >> 2;
    const int tig = lane & 3;

    int bufi = 0;
    for (int t = b; t < ntile; t += stride, bufi ^= 1) {
        const int bm0 = t * 64;

        float acc[2][8][4];
#pragma unroll
        for (int mt = 0; mt < 2; mt++)
#pragma unroll
            for (int nt = 0; nt < 8; nt++)
#pragma unroll
                for (int j = 0; j < 4; j++) acc[mt][nt][j] = 0.f;

        const uint32_t aB = aBase + (uint32_t)bufi * (64 * 264 * 2);
#pragma unroll 4
        for (int it = 0; it < 16; it++) {
            uint32_t ra[2][4];
#pragma unroll
            for (int mt = 0; mt < 2; mt++) {
                uint32_t addr = aB + (uint32_t)(wm0 + mt * 16 + (lane & 15)) * 528u
                              + (uint32_t)(lane >> 4) * 16u + (uint32_t)it * 32u;
                ldsm_x4(ra[mt], addr);
            }
#pragma unroll
            for (int p = 0; p < 4; p++) {
                uint32_t rb[4];
                uint32_t addr = bBase + (uint32_t)(it * 16 + (lane & 15)) * 528u
                              + (uint32_t)(wn0 + p * 16 + ((lane >> 4) * 8)) * 2u;
                ldsm_x4_t(rb, addr);
#pragma unroll
                for (int mt = 0; mt < 2; mt++) {
                    mma_bf16(acc[mt][2 * p + 0], ra[mt], rb + 0);
                    mma_bf16(acc[mt][2 * p + 1], ra[mt], rb + 2);
                }
            }
        }

        const int tn = t + stride;
        if (tn < ntile) loadA(tn * 64, bufi ^ 1);

#pragma unroll
        for (int nt = 0; nt < 8; nt++) {
            const int col = wn0 + nt * 8 + tig * 2;
#pragma unroll
            for (int mt = 0; mt < 2; mt++) {
                const int row0 = bm0 + wm0 + mt * 16 + groupID;
                if (row0 < M) {
                    __nv_bfloat162 h = __floats2bfloat162_rn(acc[mt][nt][0], acc[mt][nt][1]);
                    *(__nv_bfloat162*)(Y + (size_t)row0 * 256 + col) = h;
                }
                const int row1 = row0 + 8;
                if (row1 < M) {
                    __nv_bfloat162 h = __floats2bfloat162_rn(acc[mt][nt][2], acc[mt][nt][3]);
                    *(__nv_bfloat162*)(Y + (size_t)row1 * 256 + col) = h;
                }
            }
        }
        __syncthreads();
    }
}

// ---------------- gather_ep: warp-per-row bf16 Y gather + epilogue ----------
#define GR_ROWS 64
#define GR_UB   ((N_USER + GR_ROWS - 1) / GR_ROWS)   // 1563
#define GR_GB   ((N_GAME + GR_ROWS - 1) / GR_ROWS)   // 782

__global__ __launch_bounds__(256)
void gather_ep(const int* __restrict__ rp_u, const int* __restrict__ srcs_u,
               const int* __restrict__ rp_g, const int* __restrict__ srcs_g,
               const __nv_bfloat16* __restrict__ Yu, const __nv_bfloat16* __restrict__ Yg,
               const float* __restrict__ x_user, const float* __restrict__ x_game,
               const float* __restrict__ eu, const float* __restrict__ eg,
               const float* __restrict__ bout_u, const float* __restrict__ bout_g,
               float* __restrict__ out)
{
    const int lane = threadIdx.x & 31;
    const int warp = threadIdx.x >> 5;

    const bool isU = (blockIdx.x < GR_UB);
    const int r0 = (isU ? blockIdx.x : blockIdx.x - GR_UB) * GR_ROWS;
    const int M = isU ? N_USER : N_GAME;
    const int* rowptr = isU ? rp_u : rp_g;
    const int* srcs   = isU ? srcs_u : srcs_g;
    const uint4* Y4   = (const uint4*)(isU ? Yu : Yg);
    const float* Xres = isU ? x_user : x_game;
    const float* extra = isU ? eu : eg;
    const float* bout  = isU ? bout_u : bout_g;
    float* Outb = isU ? out : out + (size_t)N_USER * DDIM;

    const float4 bo0 = *(const float4*)(bout + lane * 8);
    const float4 bo1 = *(const float4*)(bout + lane * 8 + 4);
    const float4 ev0 = *(const float4*)(extra + lane * 8);
    const float4 ev1 = *(const float4*)(extra + lane * 8 + 4);

    const int rend = (r0 + GR_ROWS < M) ? r0 + GR_ROWS : M;
#pragma unroll 1
    for (int r = r0 + warp; r < rend; r += 8) {
        const int beg = __ldg(rowptr + r);
        const int end = __ldg(rowptr + r + 1);
        float acc[8];
#pragma unroll
        for (int j = 0; j < 8; j++) acc[j] = 0.f;

        int e = beg;
        for (; e + 1 < end; e += 2) {
            int s0 = __ldg(srcs + e), s1 = __ldg(srcs + e + 1);
            uint4 v0 = Y4[(size_t)s0 * 32 + lane];
            uint4 v1 = Y4[(size_t)s1 * 32 + lane];
            float2 f;
            f = __bfloat1622float2(*(__nv_bfloat162*)&v0.x); acc[0] += f.x; acc[1] += f.y;
            f = __bfloat1622float2(*(__nv_bfloat162*)&v0.y); acc[2] += f.x; acc[3] += f.y;
            f = __bfloat1622float2(*(__nv_bfloat162*)&v0.z); acc[4] += f.x; acc[5] += f.y;
            f = __bfloat1622float2(*(__nv_bfloat162*)&v0.w); acc[6] += f.x; acc[7] += f.y;
            f = __bfloat1622float2(*(__nv_bfloat162*)&v1.x); acc[0] += f.x; acc[1] += f.y;
            f = __bfloat1622float2(*(__nv_bfloat162*)&v1.y); acc[2] += f.x; acc[3] += f.y;
            f = __bfloat1622float2(*(__nv_bfloat162*)&v1.z); acc[4] += f.x; acc[5] += f.y;
            f = __bfloat1622float2(*(__nv_bfloat162*)&v1.w); acc[6] += f.x; acc[7] += f.y;
        }
        if (e < end) {
            int s0 = __ldg(srcs + e);
            uint4 v0 = Y4[(size_t)s0 * 32 + lane];
            float2 f;
            f = __bfloat1622float2(*(__nv_bfloat162*)&v0.x); acc[0] += f.x; acc[1] += f.y;
            f = __bfloat1622float2(*(__nv_bfloat162*)&v0.y); acc[2] += f.x; acc[3] += f.y;
            f = __bfloat1622float2(*(__nv_bfloat162*)&v0.z); acc[4] += f.x; acc[5] += f.y;
            f = __bfloat1622float2(*(__nv_bfloat162*)&v0.w); acc[6] += f.x; acc[7] += f.y;
        }

        const int deg = end - beg;
        const float inv = 1.0f / (float)(deg > 1 ? deg : 1);
        const float on = (deg > 0) ? 1.0f : 0.0f;
        const float4 x0 = *(const float4*)(Xres + (size_t)r * 256 + lane * 8);
        const float4 x1 = *(const float4*)(Xres + (size_t)r * 256 + lane * 8 + 4);
        float4 o0, o1;
        o0.x = fmaxf(acc[0] * inv + bo0.x + on * ev0.x + x0.x, 0.f);
        o0.y = fmaxf(acc[1] * inv + bo0.y + on * ev0.y + x0.y, 0.f);
        o0.z = fmaxf(acc[2] * inv + bo0.z + on * ev0.z + x0.z, 0.f);
        o0.w = fmaxf(acc[3] * inv + bo0.w + on * ev0.w + x0.w, 0.f);
        o1.x = fmaxf(acc[4] * inv + bo1.x + on * ev1.x + x1.x, 0.f);
        o1.y = fmaxf(acc[5] * inv + bo1.y + on * ev1.y + x1.y, 0.f);
        o1.z = fmaxf(acc[6] * inv + bo1.z + on * ev1.z + x1.z, 0.f);
        o1.w = fmaxf(acc[7] * inv + bo1.w + on * ev1.w + x1.w, 0.f);
        *(float4*)(Outb + (size_t)r * 256 + lane * 8) = o0;
        *(float4*)(Outb + (size_t)r * 256 + lane * 8 + 4) = o1;
    }
}

// ---------------- host launch ----------------
extern "C" void kernel_launch(void* const* d_in, const int* in_sizes, int n_in,
                              void* d_out, int out_size)
{
    const float* x_user    = (const float*)d_in[0];
    const float* x_game    = (const float*)d_in[1];
    const float* Wv_user   = (const float*)d_in[6];
    const float* bv_user   = (const float*)d_in[7];
    const float* Wout_user = (const float*)d_in[8];
    const float* bout_user = (const float*)d_in[9];
    const float* Wv_game   = (const float*)d_in[14];
    const float* bv_game   = (const float*)d_in[15];
    const float* Wout_game = (const float*)d_in[16];
    const float* bout_game = (const float*)d_in[17];
    const float* Wm_played = (const float*)d_in[20];
    const float* bm_played = (const float*)d_in[21];
    const float* Wm_rev    = (const float*)d_in[24];
    const float* bm_rev    = (const float*)d_in[25];
    const int* ps = (const int*)d_in[26];
    const int* pd = (const int*)d_in[27];
    const int* rs = (const int*)d_in[28];
    const int* rd = (const int*)d_in[29];
    const int E = in_sizes[26];

    float* out = (float*)d_out;

    float *tmpA, *tmpB, *eu, *eg;
    int *rp_u, *rp_g, *cur_u, *cur_g, *srcs_u, *srcs_g, *part_u, *part_g;
    __nv_bfloat16 *Wub, *Wgb, *Yg, *Yu;
    cudaGetSymbolAddress((void**)&rp_u,   g_rp_u);
    cudaGetSymbolAddress((void**)&rp_g,   g_rp_g);
    cudaGetSymbolAddress((void**)&cur_u,  g_cur_u);
    cudaGetSymbolAddress((void**)&cur_g,  g_cur_g);
    cudaGetSymbolAddress((void**)&srcs_u, g_srcs_u);
    cudaGetSymbolAddress((void**)&srcs_g, g_srcs_g);
    cudaGetSymbolAddress((void**)&part_u, g_part_u);
    cudaGetSymbolAddress((void**)&part_g, g_part_g);
    cudaGetSymbolAddress((void**)&tmpA,   g_tmpA);
    cudaGetSymbolAddress((void**)&tmpB,   g_tmpB);
    cudaGetSymbolAddress((void**)&Wub,    g_Wub);
    cudaGetSymbolAddress((void**)&Wgb,    g_Wgb);
    cudaGetSymbolAddress((void**)&eu,     g_eu);
    cudaGetSymbolAddress((void**)&eg,     g_eg);
    cudaGetSymbolAddress((void**)&Yg,     g_Yg);
    cudaGetSymbolAddress((void**)&Yu,     g_Yu);

    cudaFuncSetAttribute(gemmY,
                         cudaFuncAttributeMaxDynamicSharedMemorySize, SMP_TOTAL);

    const int len_u = N_USER + 1, len_g = N_GAME + 1;
    const int sgx = (len_u + 1023) / 1024;
    const bool fork = (g_s2 != 0);
    cudaStream_t s2 = fork ? g_s2 : 0;

    // main stream: zero rowptrs, then weight GEMM + histogram
    cudaMemsetAsync(rp_u, 0, (size_t)(N_USER + 1) * sizeof(int));
    cudaMemsetAsync(rp_g, 0, (size_t)(N_GAME + 1) * sizeof(int));

    // idx 2: weight-chain GEMM pair + histogram (also the CSR fork point)
    k0_gemm_hist<<<dim3(4, 4, 4), 256>>>(Wm_played, Wout_game, tmpA,
                                         Wm_rev, Wout_user, tmpB,
                                         pd, rd, E, rp_g, rp_u);
    if (fork) {
        cudaEventRecord(g_e1, 0);
        cudaStreamWaitEvent(s2, g_e1, 0);
    }

    // idx 3 (main): bf16 weight GEMM pair + bias combo
    k1_gemmbf_combo<<<dim3(4, 4, 3), 256>>>(Wv_user, tmpA, Wgb,
                                            Wv_game, tmpB, Wub, 0.125f,
                                            bv_user, tmpA, bm_played, Wout_game, eg,
                                            bv_game, tmpB, bm_rev, Wout_user, eu);
    // idx 4 (side): scan partials
    scanA<<<dim3(sgx, 2), 1024, 0, s2>>>(rp_u, len_u, part_u, rp_g, len_g, part_g);
    // idx 5 (main, profiled): persistent GEMM Y = bf16(X @ Wcombined)
    gemmY<<<BLK_U + BLK_G, 256, SMP_TOTAL>>>(x_user, x_game, Wgb, Wub, Yg, Yu);
    // idx 6 (side): finish scan + cursor init
    scanC<<<dim3(sgx, 2), 1024, 0, s2>>>(rp_u, len_u, part_u, cur_u,
                                         rp_g, len_g, part_g, cur_g);
    // idx 7 (side): bin edges into CSR
    bin_kernel<<<(E + 255) / 256, 256, 0, s2>>>(ps, pd, rs, rd, E,
                                                cur_g, srcs_g, cur_u, srcs_u);
    if (fork) {
        cudaEventRecord(g_e2, s2);
        cudaStreamWaitEvent(0, g_e2, 0);
    }
    // idx 8 (main): bf16 gather + epilogue
    gather_ep<<<GR_UB + GR_GB, 256>>>(rp_u, srcs_u, rp_g, srcs_g, Yu, Yg,
                                      x_user, x_game, eu, eg,
                                      bout_user, bout_game, out);
}